// round 11
// baseline (speedup 1.0000x reference)
#include <cuda_runtime.h>
#include <cuda_bf16.h>
#include <stdint.h>
#include <math.h>

// Problem constants
#define NROWS 30000
#define HH    8
#define SD    17          // OT+1
#define OSD   240
#define DD    257         // IN_DIM == OUT_DIM
#define FF    2056        // H * 257
#define LDP   144         // padded pair-stride for packed X/W (16B-aligned rows)
#define CHP   960         // pair-stride for packed ch (K=1920)
#define KTP   128         // padded pair-stride for packed ktv rows (120->128)

// ---------------- scratch (device globals; no runtime alloc allowed) -------
__device__ float    g_Yq[NROWS * FF];
__device__ float    g_Yk[NROWS * FF];
__device__ float    g_Yv[NROWS * FF];
__device__ float    g_ktvT[HH * DD * DD];  // ktvT[h][d][m] (h-block only)
__device__ float    g_ktvs[HH * SD * SD];  // s-block ktv[h][m][d]
__device__ float    g_sumK[FF];
__device__ float    g_denS[NROWS * HH];
__device__ float    g_denH[NROWS * HH];
__device__ float    g_cs[NROWS * HH * SD];
__device__ float    g_atts[NROWS * SD];
__device__ float    g_b[NROWS * OSD];
// packed operands (hi/lo bf16x2)
__device__ uint32_t g_Xq_hi[NROWS * LDP], g_Xq_lo[NROWS * LDP];
__device__ uint32_t g_Xs_hi[NROWS * LDP], g_Xs_lo[NROWS * LDP];
__device__ uint32_t g_Wq_hi[FF * LDP],    g_Wq_lo[FF * LDP];
__device__ uint32_t g_Wk_hi[FF * LDP],    g_Wk_lo[FF * LDP];
__device__ uint32_t g_Wv_hi[FF * LDP],    g_Wv_lo[FF * LDP];
__device__ uint32_t g_Wh_hi[OSD * CHP],   g_Wh_lo[OSD * CHP];
__device__ uint32_t g_ch_hi[NROWS * CHP], g_ch_lo[NROWS * CHP];   // packed attention output
__device__ uint32_t g_ktvp_hi[HH * OSD * KTP], g_ktvp_lo[HH * OSD * KTP];

// ---------------------------------------------------------------------------
__device__ __forceinline__ void mma16816(float c[4], const uint32_t a[4], const uint32_t b0, const uint32_t b1)
{
    asm volatile(
        "mma.sync.aligned.m16n8k16.row.col.f32.bf16.bf16.f32 "
        "{%0,%1,%2,%3}, {%4,%5,%6,%7}, {%8,%9}, {%0,%1,%2,%3};\n"
        : "+f"(c[0]), "+f"(c[1]), "+f"(c[2]), "+f"(c[3])
        : "r"(a[0]), "r"(a[1]), "r"(a[2]), "r"(a[3]), "r"(b0), "r"(b1));
}

__device__ __forceinline__ void ldsm_x4(uint32_t& r0, uint32_t& r1, uint32_t& r2, uint32_t& r3, uint32_t addr)
{
    asm volatile("ldmatrix.sync.aligned.m8n8.x4.shared.b16 {%0,%1,%2,%3}, [%4];"
                 : "=r"(r0), "=r"(r1), "=r"(r2), "=r"(r3) : "r"(addr));
}

__device__ __forceinline__ uint32_t smem_addr(const void* p)
{
    return (uint32_t)__cvta_generic_to_shared(p);
}

__device__ __forceinline__ void cp_async16(uint32_t dst, const void* src, int src_bytes)
{
    asm volatile("cp.async.cg.shared.global [%0], [%1], 16, %2;"
                 :: "r"(dst), "l"(src), "r"(src_bytes));
}

__device__ __forceinline__ void cvt_pack(float x0, float x1, uint32_t& hp, uint32_t& lp)
{
    __nv_bfloat16 h0 = __float2bfloat16(x0);
    __nv_bfloat16 h1 = __float2bfloat16(x1);
    __nv_bfloat16 l0 = __float2bfloat16(x0 - __bfloat162float(h0));
    __nv_bfloat16 l1 = __float2bfloat16(x1 - __bfloat162float(h1));
    __nv_bfloat162 hh; hh.x = h0; hh.y = h1;
    __nv_bfloat162 ll; ll.x = l0; ll.y = l1;
    hp = *reinterpret_cast<uint32_t*>(&hh);
    lp = *reinterpret_cast<uint32_t*>(&ll);
}

// --------- pack fp32 matrix into bf16x2 hi/lo pair arrays (ldp-padded) -----
__global__ void pack_kernel(const float* __restrict__ src,
                            uint32_t* __restrict__ hi, uint32_t* __restrict__ lo,
                            int rows, int K, int ld, int ldp)
{
    int idx = blockIdx.x * blockDim.x + threadIdx.x;
    if (idx >= rows * ldp) return;
    int r_ = idx / ldp, kp = idx - r_ * ldp;
    int k = kp * 2;
    float x0 = (k < K)     ? src[r_ * ld + k]     : 0.f;
    float x1 = (k + 1 < K) ? src[r_ * ld + k + 1] : 0.f;
    uint32_t hp, lp; cvt_pack(x0, x1, hp, lp);
    hi[idx] = hp; lo[idx] = lp;
}

// --------- pack ktvT h-block rows into per-head [d][KTP] pair arrays -------
__global__ void ktvp_pack_kernel(const float* __restrict__ ktvT,
                                 uint32_t* __restrict__ hi, uint32_t* __restrict__ lo)
{
    int idx = blockIdx.x * blockDim.x + threadIdx.x;
    if (idx >= HH * OSD * KTP) return;
    int h  = idx / (OSD * KTP);
    int rm = idx - h * (OSD * KTP);
    int d  = rm / KTP;
    int kp = rm - d * KTP;
    int k = kp * 2;
    const float* src = ktvT + h * DD * DD + (d + SD) * DD + SD;
    float x0 = (k     < OSD) ? src[k]     : 0.f;
    float x1 = (k + 1 < OSD) ? src[k + 1] : 0.f;
    uint32_t hp, lp; cvt_pack(x0, x1, hp, lp);
    hi[idx] = hp; lo[idx] = lp;
}

// ---------------------------------------------------------------------------
// Packed double-buffered GEMM (cp.async): C[m,n] = sum_k A[m,k]*B[n,k].
// Both operands pre-packed bf16x2 hi/lo. Requires lda_p,ldb_p >= ceil16(KP)*16.
// ---------------------------------------------------------------------------
#define STAGE_BYTES 40960
#define ARR_BYTES   10240
__global__ __launch_bounds__(256, 2) void gemm_pp_db(
    const uint32_t* __restrict__ Apk_h, const uint32_t* __restrict__ Apk_l,
    const uint32_t* __restrict__ Bpk_h, const uint32_t* __restrict__ Bpk_l,
    float* __restrict__ C,
    int M, int N, int KP, int lda_p, int ldb_p, int ldc, int phiH)
{
    extern __shared__ char smem[];
    const uint32_t smem_u32 = smem_addr(smem);

    const int tid  = threadIdx.x;
    const int lane = tid & 31;
    const int wid  = tid >> 5;
    const int wm   = wid & 3;
    const int wn   = wid >> 2;
    const int row0 = blockIdx.y * 128;
    const int col0 = blockIdx.x * 128;
    const int r    = lane >> 2;
    const int q4   = lane & 3;

    const int aRow = (lane & 15);
    const int aCol = (lane >> 4) * 4;
    const int bRow = (lane & 7) + ((lane >> 4) << 3);
    const int bCol = ((lane >> 3) & 1) * 4;

    float acc[2][8][4];
#pragma unroll
    for (int mt = 0; mt < 2; mt++)
#pragma unroll
        for (int nt = 0; nt < 8; nt++)
#pragma unroll
            for (int i = 0; i < 4; i++) acc[mt][nt][i] = 0.f;

    const int KT = (KP + 15) >> 4;

    auto fill = [&](int kt, int s) {
        int kp0 = kt * 16;
        uint32_t stage = smem_u32 + s * STAGE_BYTES;
#pragma unroll
        for (int t = 0; t < 2; t++) {
            int ci  = tid + t * 256;
            int m   = ci >> 2;
            int cp4 = (ci & 3) * 4;
            uint32_t doff = (uint32_t)(m * 20 + cp4) * 4u;
            int gm = row0 + m;
            long aoff = (long)gm * lda_p + kp0 + cp4;
            int szA = (gm < M) ? 16 : 0;
            cp_async16(stage + doff,                 Apk_h + aoff, szA);
            cp_async16(stage + ARR_BYTES + doff,     Apk_l + aoff, szA);
            int gn = col0 + m;
            long boff = (long)gn * ldb_p + kp0 + cp4;
            int szB = (gn < N) ? 16 : 0;
            cp_async16(stage + 2 * ARR_BYTES + doff, Bpk_h + boff, szB);
            cp_async16(stage + 3 * ARR_BYTES + doff, Bpk_l + boff, szB);
        }
    };

    fill(0, 0);
    asm volatile("cp.async.commit_group;");

    for (int kt = 0; kt < KT; kt++) {
        int s = kt & 1;
        if (kt + 1 < KT) {
            fill(kt + 1, (kt + 1) & 1);
            asm volatile("cp.async.commit_group;");
            asm volatile("cp.async.wait_group 1;");
        } else {
            asm volatile("cp.async.wait_group 0;");
        }
        __syncthreads();

        uint32_t baseAh = smem_u32 + s * STAGE_BYTES;
        uint32_t baseAl = baseAh + ARR_BYTES;
        uint32_t baseBh = baseAh + 2 * ARR_BYTES;
        uint32_t baseBl = baseAh + 3 * ARR_BYTES;

#pragma unroll
        for (int ks = 0; ks < 2; ks++) {
            uint32_t ah[2][4], al[2][4];
#pragma unroll
            for (int mt = 0; mt < 2; mt++) {
                uint32_t off = (uint32_t)((wm * 32 + mt * 16 + aRow) * 20 + ks * 8 + aCol) * 4u;
                ldsm_x4(ah[mt][0], ah[mt][1], ah[mt][2], ah[mt][3], baseAh + off);
                ldsm_x4(al[mt][0], al[mt][1], al[mt][2], al[mt][3], baseAl + off);
            }
#pragma unroll
            for (int ntp = 0; ntp < 4; ntp++) {
                uint32_t off = (uint32_t)((wn * 64 + ntp * 16 + bRow) * 20 + ks * 8 + bCol) * 4u;
                uint32_t bh[4], bl[4];
                ldsm_x4(bh[0], bh[1], bh[2], bh[3], baseBh + off);
                ldsm_x4(bl[0], bl[1], bl[2], bl[3], baseBl + off);
#pragma unroll
                for (int sub = 0; sub < 2; sub++) {
                    int nt = ntp * 2 + sub;
#pragma unroll
                    for (int mt = 0; mt < 2; mt++) {
                        mma16816(acc[mt][nt], ah[mt], bh[sub * 2], bh[sub * 2 + 1]);
                        mma16816(acc[mt][nt], al[mt], bh[sub * 2], bh[sub * 2 + 1]);
                        mma16816(acc[mt][nt], ah[mt], bl[sub * 2], bl[sub * 2 + 1]);
                    }
                }
            }
        }
        __syncthreads();
    }

#pragma unroll
    for (int mt = 0; mt < 2; mt++) {
        int rm0 = row0 + wm * 32 + mt * 16 + r;
        int rm1 = rm0 + 8;
#pragma unroll
        for (int nt = 0; nt < 8; nt++) {
            int cn = col0 + wn * 64 + nt * 8 + q4 * 2;
#pragma unroll
            for (int jj = 0; jj < 2; jj++) {
                int gn = cn + jj;
                if (gn >= N) continue;
                bool phi = phiH && (gn % DD) >= SD;
                if (rm0 < M) {
                    float v = acc[mt][nt][jj];
                    if (phi) v = (v > 0.f) ? v + 1.f : __expf(v);
                    C[rm0 * ldc + gn] = v;
                }
                if (rm1 < M) {
                    float v = acc[mt][nt][2 + jj];
                    if (phi) v = (v > 0.f) ? v + 1.f : __expf(v);
                    C[rm1 * ldc + gn] = v;
                }
            }
        }
    }
}

// ---------------------------------------------------------------------------
// h-part attention GEMM: A = Yq h-part (fp32, in-loop cvt), B = packed ktvp.
// Epilogue: divide by dH and store ch as packed bf16x2 hi/lo pairs.
// ---------------------------------------------------------------------------
__global__ __launch_bounds__(256, 2) void attn_gemm(
    const float* __restrict__ Yq,
    const uint32_t* __restrict__ Bpk_h, const uint32_t* __restrict__ Bpk_l,
    const float* __restrict__ dH,
    uint32_t* __restrict__ ch_hi, uint32_t* __restrict__ ch_lo)
{
    __shared__ uint32_t Ah[128][20], Al[128][20], Bh[128][20], Bl[128][20];

    const int h = blockIdx.z;
    const float* A = Yq + h * DD + SD;
    const uint32_t* Bph = Bpk_h + h * OSD * KTP;
    const uint32_t* Bpl = Bpk_l + h * OSD * KTP;

    const int tid  = threadIdx.x;
    const int lane = tid & 31;
    const int wid  = tid >> 5;
    const int wm   = wid & 3;
    const int wn   = wid >> 2;
    const int row0 = blockIdx.y * 128;
    const int col0 = blockIdx.x * 128;
    const int r    = lane >> 2;
    const int q4   = lane & 3;

    const int aRow = (lane & 15);
    const int aCol = (lane >> 4) * 4;
    const int bRow = (lane & 7) + ((lane >> 4) << 3);
    const int bCol = ((lane >> 3) & 1) * 4;

    float acc[2][8][4];
#pragma unroll
    for (int mt = 0; mt < 2; mt++)
#pragma unroll
        for (int nt = 0; nt < 8; nt++)
#pragma unroll
            for (int i = 0; i < 4; i++) acc[mt][nt][i] = 0.f;

    for (int kt = 0; kt < 8; kt++) {
        int k0 = kt * 32;
        // A fill: fp32 strided gather + cvt
#pragma unroll
        for (int i = 0; i < 8; i++) {
            int idx = tid + i * 256;
            int m = idx >> 4, kp = idx & 15;
            int gm = row0 + m, gk = k0 + kp * 2;
            float x0 = (gm < NROWS && gk     < OSD) ? __ldg(&A[gm * FF + gk])     : 0.f;
            float x1 = (gm < NROWS && gk + 1 < OSD) ? __ldg(&A[gm * FF + gk + 1]) : 0.f;
            uint32_t hp, lp; cvt_pack(x0, x1, hp, lp);
            Ah[m][kp] = hp; Al[m][kp] = lp;
        }
        // B fill: packed u32 loads, no cvt
#pragma unroll
        for (int i = 0; i < 8; i++) {
            int idx = tid + i * 256;
            int n = idx >> 4, kp = idx & 15;
            int gn = col0 + n;
            int gkp = kt * 16 + kp;  // 0..127, padded zeros beyond 120
            bool ok = (gn < OSD);
            Bh[n][kp] = ok ? __ldg(&Bph[gn * KTP + gkp]) : 0u;
            Bl[n][kp] = ok ? __ldg(&Bpl[gn * KTP + gkp]) : 0u;
        }
        __syncthreads();

#pragma unroll
        for (int ks = 0; ks < 2; ks++) {
            uint32_t ah[2][4], al[2][4];
#pragma unroll
            for (int mt = 0; mt < 2; mt++) {
                int m_ = wm * 32 + mt * 16 + aRow;
                int c_ = ks * 8 + aCol;
                ldsm_x4(ah[mt][0], ah[mt][1], ah[mt][2], ah[mt][3], smem_addr(&Ah[m_][c_]));
                ldsm_x4(al[mt][0], al[mt][1], al[mt][2], al[mt][3], smem_addr(&Al[m_][c_]));
            }
#pragma unroll
            for (int ntp = 0; ntp < 4; ntp++) {
                int n_ = wn * 64 + ntp * 16 + bRow;
                int c_ = ks * 8 + bCol;
                uint32_t bh[4], bl[4];
                ldsm_x4(bh[0], bh[1], bh[2], bh[3], smem_addr(&Bh[n_][c_]));
                ldsm_x4(bl[0], bl[1], bl[2], bl[3], smem_addr(&Bl[n_][c_]));
#pragma unroll
                for (int sub = 0; sub < 2; sub++) {
                    int nt = ntp * 2 + sub;
#pragma unroll
                    for (int mt = 0; mt < 2; mt++) {
                        mma16816(acc[mt][nt], ah[mt], bh[sub * 2], bh[sub * 2 + 1]);
                        mma16816(acc[mt][nt], al[mt], bh[sub * 2], bh[sub * 2 + 1]);
                        mma16816(acc[mt][nt], ah[mt], bl[sub * 2], bl[sub * 2 + 1]);
                    }
                }
            }
        }
        __syncthreads();
    }

    // epilogue: divide by dH, pack pair (d, d+1) -> ch_hi/ch_lo
#pragma unroll
    for (int mt = 0; mt < 2; mt++) {
        int rm0 = row0 + wm * 32 + mt * 16 + r;
        int rm1 = rm0 + 8;
        float dh0 = 1.f, dh1 = 1.f;
        if (rm0 < NROWS) dh0 = dH[rm0 * HH + h] + 1e-8f;
        if (rm1 < NROWS) dh1 = dH[rm1 * HH + h] + 1e-8f;
#pragma unroll
        for (int nt = 0; nt < 8; nt++) {
            int cn = col0 + wn * 64 + nt * 8 + q4 * 2;   // even, pair (cn, cn+1)
            if (cn >= OSD) continue;
            int pidx = (h * OSD + cn) >> 1;
            if (rm0 < NROWS) {
                uint32_t hp, lp;
                cvt_pack(acc[mt][nt][0] / dh0, acc[mt][nt][1] / dh0, hp, lp);
                ch_hi[rm0 * CHP + pidx] = hp; ch_lo[rm0 * CHP + pidx] = lp;
            }
            if (rm1 < NROWS) {
                uint32_t hp, lp;
                cvt_pack(acc[mt][nt][2] / dh1, acc[mt][nt][3] / dh1, hp, lp);
                ch_hi[rm1 * CHP + pidx] = hp; ch_lo[rm1 * CHP + pidx] = lp;
            }
        }
    }
}

// ---------------------------------------------------------------------------
// ktv h-block (TN): ktvT[h][d+SD][m+SD] = sum_n phiKh[n,m] * Vh[n,d]
// ---------------------------------------------------------------------------
#define KTV_NSPLIT 20
__global__ __launch_bounds__(256, 2) void ktv_bf16s_tn(
    const float* __restrict__ Yk, const float* __restrict__ Yv,
    float* __restrict__ ktvT)
{
    __shared__ uint32_t Ah[128][20], Al[128][20], Bh[128][20], Bl[128][20];

    const int h  = blockIdx.z / KTV_NSPLIT;
    const int sp = blockIdx.z % KTV_NSPLIT;
    const int m0 = blockIdx.x * 128;
    const int d0 = blockIdx.y * 128;
    const int chunk = (NROWS + KTV_NSPLIT - 1) / KTV_NSPLIT;
    const int n0 = sp * chunk;
    int n1 = n0 + chunk; if (n1 > NROWS) n1 = NROWS;

    const float* Kp = Yk + h * DD + SD;
    const float* Vp = Yv + h * DD + SD;

    const int tid  = threadIdx.x;
    const int lane = tid & 31;
    const int wid  = tid >> 5;
    const int wm   = wid & 3;
    const int wn   = wid >> 2;
    const int r    = lane >> 2;
    const int q4   = lane & 3;

    const int aRow = (lane & 15);
    const int aCol = (lane >> 4) * 4;
    const int bRow = (lane & 7) + ((lane >> 4) << 3);
    const int bCol = ((lane >> 3) & 1) * 4;

    float acc[2][8][4];
#pragma unroll
    for (int mt = 0; mt < 2; mt++)
#pragma unroll
        for (int nt = 0; nt < 8; nt++)
#pragma unroll
            for (int i = 0; i < 4; i++) acc[mt][nt][i] = 0.f;

    for (int kb = n0; kb < n1; kb += 32) {
#pragma unroll
        for (int i = 0; i < 8; i++) {
            int idx = tid + i * 256;
            int m = idx & 127, np = idx >> 7;
            int gm = m0 + m;
            int gn = kb + np * 2;
            bool mok = (gm < OSD);
            float x0 = (mok && gn     < n1) ? __ldg(&Kp[gn * FF + gm])       : 0.f;
            float x1 = (mok && gn + 1 < n1) ? __ldg(&Kp[(gn + 1) * FF + gm]) : 0.f;
            uint32_t hp, lp; cvt_pack(x0, x1, hp, lp);
            Ah[m][np] = hp; Al[m][np] = lp;
        }
#pragma unroll
        for (int i = 0; i < 8; i++) {
            int idx = tid + i * 256;
            int d = idx & 127, np = idx >> 7;
            int gd = d0 + d;
            int gn = kb + np * 2;
            bool dok = (gd < OSD);
            float x0 = (dok && gn     < n1) ? __ldg(&Vp[gn * FF + gd])       : 0.f;
            float x1 = (dok && gn + 1 < n1) ? __ldg(&Vp[(gn + 1) * FF + gd]) : 0.f;
            uint32_t hp, lp; cvt_pack(x0, x1, hp, lp);
            Bh[d][np] = hp; Bl[d][np] = lp;
        }
        __syncthreads();

#pragma unroll
        for (int ks = 0; ks < 2; ks++) {
            uint32_t ah[2][4], al[2][4];
#pragma unroll
            for (int mt = 0; mt < 2; mt++) {
                int m_ = wm * 32 + mt * 16 + aRow;
                int c_ = ks * 8 + aCol;
                ldsm_x4(ah[mt][0], ah[mt][1], ah[mt][2], ah[mt][3], smem_addr(&Ah[m_][c_]));
                ldsm_x4(al[mt][0], al[mt][1], al[mt][2], al[mt][3], smem_addr(&Al[m_][c_]));
            }
#pragma unroll
            for (int ntp = 0; ntp < 4; ntp++) {
                int n_ = wn * 64 + ntp * 16 + bRow;
                int c_ = ks * 8 + bCol;
                uint32_t bh[4], bl[4];
                ldsm_x4(bh[0], bh[1], bh[2], bh[3], smem_addr(&Bh[n_][c_]));
                ldsm_x4(bl[0], bl[1], bl[2], bl[3], smem_addr(&Bl[n_][c_]));
#pragma unroll
                for (int sub = 0; sub < 2; sub++) {
                    int nt = ntp * 2 + sub;
#pragma unroll
                    for (int mt = 0; mt < 2; mt++) {
                        mma16816(acc[mt][nt], ah[mt], bh[sub * 2], bh[sub * 2 + 1]);
                        mma16816(acc[mt][nt], al[mt], bh[sub * 2], bh[sub * 2 + 1]);
                        mma16816(acc[mt][nt], ah[mt], bl[sub * 2], bl[sub * 2 + 1]);
                    }
                }
            }
        }
        __syncthreads();
    }

    float* kt = ktvT + h * DD * DD;
#pragma unroll
    for (int mt = 0; mt < 2; mt++) {
        int gm0 = m0 + wm * 32 + mt * 16 + r;
        int gm1 = gm0 + 8;
#pragma unroll
        for (int nt = 0; nt < 8; nt++) {
            int gd = d0 + wn * 64 + nt * 8 + q4 * 2;
#pragma unroll
            for (int jj = 0; jj < 2; jj++) {
                int d = gd + jj;
                if (d >= OSD) continue;
                if (gm0 < OSD) atomicAdd(&kt[(d + SD) * DD + (gm0 + SD)], acc[mt][nt][jj]);
                if (gm1 < OSD) atomicAdd(&kt[(d + SD) * DD + (gm1 + SD)], acc[mt][nt][2 + jj]);
            }
        }
    }
}

// --------- s-block ktv ------------------------------------------------------
#define KTVS_NCHUNK 100
__global__ __launch_bounds__(320) void ktvs_kernel(
    const float* __restrict__ Yk, const float* __restrict__ Yv,
    float* __restrict__ ktvs)
{
    __shared__ float sk[SD], sv[SD];
    int h  = blockIdx.y;
    int cn = blockIdx.x;
    int chunk = (NROWS + KTVS_NCHUNK - 1) / KTVS_NCHUNK;
    int n0 = cn * chunk;
    int n1 = n0 + chunk; if (n1 > NROWS) n1 = NROWS;
    int t = threadIdx.x;
    int m = t / SD, d = t - m * SD;
    bool act = (t < SD * SD);
    float acc = 0.f;
    for (int n = n0; n < n1; n++) {
        if (t < SD)            sk[t]      = Yk[n * FF + h * DD + t];
        else if (t < 2 * SD)   sv[t - SD] = Yv[n * FF + h * DD + (t - SD)];
        __syncthreads();
        if (act) acc += sk[m] * sv[d];
        __syncthreads();
    }
    if (act) atomicAdd(&ktvs[h * SD * SD + m * SD + d], acc);
}

// --------- s-part attention fused: cs = (phiQs @ ktvs) / denS --------------
__global__ void cs_kernel(const float* __restrict__ Yq,
                          const float* __restrict__ ktvs,
                          const float* __restrict__ dS,
                          float* __restrict__ cs)
{
    int warp = (blockIdx.x * blockDim.x + threadIdx.x) >> 5;
    int lane = threadIdx.x & 31;
    if (warp >= NROWS * HH) return;
    int n = warp / HH, h = warp - n * HH;
    const float* q = Yq + n * FF + h * DD;
    const float* kt = ktvs + h * SD * SD;
    float qv = (lane < SD) ? q[lane] : 0.f;
    float acc = 0.f;
#pragma unroll
    for (int m = 0; m < SD; m++) {
        float qm = __shfl_sync(0xffffffffu, qv, m);
        if (lane < SD) acc += qm * kt[m * SD + lane];
    }
    if (lane < SD) cs[n * (HH * SD) + h * SD + lane] = acc / (dS[n * HH + h] + 1e-6f);
}

// --------- s-part pseudo-linear fixup --------------------------------------
__global__ void ep1s_kernel(float* __restrict__ Y, int do_phi)
{
    int warp = (blockIdx.x * blockDim.x + threadIdx.x) >> 5;
    int lane = threadIdx.x & 31;
    if (warp >= NROWS * HH) return;
    int n = warp / HH, h = warp - n * HH;
    float* p = Y + n * FF + h * DD;
    float x = (lane < SD) ? p[lane] : 0.f;
    float ss = x * x;
#pragma unroll
    for (int o = 16; o > 0; o >>= 1) ss += __shfl_xor_sync(0xffffffffu, ss, o);
    float scale = 1.f / (sqrtf(ss) + 1e-8f);
    if (lane < SD) {
        float y = x * scale;
        if (do_phi) y = (y > 0.f) ? y + 1.f : __expf(y);
        p[lane] = y;
    }
}

__global__ void zero_kernel(float* __restrict__ p, int n)
{
    int i = blockIdx.x * blockDim.x + threadIdx.x;
    if (i < n) p[i] = 0.f;
}

// --------- column sums of phiK ---------------------------------------------
__global__ void colsum_kernel(const float* __restrict__ Y, float* __restrict__ out)
{
    int f = blockIdx.x * blockDim.x + threadIdx.x;
    if (f >= FF) return;
    int n0 = blockIdx.y * 750;
    int n1 = n0 + 750; if (n1 > NROWS) n1 = NROWS;
    float s = 0.f;
    for (int n = n0; n < n1; n++) s += Y[n * FF + f];
    atomicAdd(&out[f], s);
}

// --------- den_s / den_h per (n,h) -----------------------------------------
__global__ void den_kernel(const float* __restrict__ PQ,
                           const float* __restrict__ sumK,
                           float* __restrict__ dS, float* __restrict__ dH)
{
    int n = blockIdx.x;
    int h = threadIdx.x >> 5;
    int lane = threadIdx.x & 31;
    const float* p = PQ + n * FF + h * DD;
    const float* s = sumK + h * DD;
    float as = 0.f, ah = 0.f;
    for (int m = lane; m < DD; m += 32) {
        float v = p[m] * s[m];
        if (m < SD) as += v; else ah += v;
    }
#pragma unroll
    for (int o = 16; o > 0; o >>= 1) {
        as += __shfl_xor_sync(0xffffffffu, as, o);
        ah += __shfl_xor_sync(0xffffffffu, ah, o);
    }
    if (lane == 0) { dS[n * HH + h] = as; dH[n * HH + h] = ah; }
}

// --------- a = c_s @ Ws^T, att_s = a / max(||a||,1e-12) --------------------
__global__ void a_kernel(const float* __restrict__ cs,
                         const float* __restrict__ Ws,
                         float* __restrict__ atts)
{
    __shared__ float ws[SD * 136];
    for (int i = threadIdx.x; i < SD * 136; i += blockDim.x) ws[i] = Ws[i];
    __syncthreads();
    int warp = threadIdx.x >> 5, lane = threadIdx.x & 31;
    int n = blockIdx.x * 8 + warp;
    if (n >= NROWS) return;
    float acc[SD];
#pragma unroll
    for (int o = 0; o < SD; o++) acc[o] = 0.f;
    for (int f = lane; f < 136; f += 32) {
        float x = cs[n * 136 + f];
#pragma unroll
        for (int o = 0; o < SD; o++) acc[o] += x * ws[o * 136 + f];
    }
#pragma unroll
    for (int o = 0; o < SD; o++)
#pragma unroll
        for (int s = 16; s > 0; s >>= 1)
            acc[o] += __shfl_xor_sync(0xffffffffu, acc[o], s);
    if (lane == 0) {
        float ss = 0.f;
#pragma unroll
        for (int o = 0; o < SD; o++) ss += acc[o] * acc[o];
        float sc = 1.f / fmaxf(sqrtf(ss), 1e-12f);
#pragma unroll
        for (int o = 0; o < SD; o++) atts[n * SD + o] = acc[o] * sc;
    }
}

// --------- final epilogue ---------------------------------------------------
__global__ void final_kernel(const float* __restrict__ b,
                             const float* __restrict__ atts,
                             float* __restrict__ out)
{
    int warp = threadIdx.x >> 5, lane = threadIdx.x & 31;
    int n = blockIdx.x * 8 + warp;
    if (n >= NROWS) return;
    const float* br = b + n * OSD;
    float ss = 0.f;
    for (int j = lane; j < OSD; j += 32) { float v = br[j]; ss += v * v; }
#pragma unroll
    for (int s = 16; s > 0; s >>= 1) ss += __shfl_xor_sync(0xffffffffu, ss, s);
    float nr  = sqrtf(ss);
    float bn  = nr + 1e-8f;
    float bnc = fminf(bn, 1e6f);
    float bt  = sqrtf(bnc * bnc + 1.0f);
    float scale = (bn > 1e6f) ? (1e6f / fmaxf(nr, 1e-12f * bnc)) : 1.0f;
    float* o = out + n * DD;
    for (int j = lane; j < OSD; j += 32) o[SD + j] = br[j] * scale;
    if (lane < SD) o[lane] = bt * atts[n * SD + lane];
}

// ---------------------------------------------------------------------------
extern "C" void kernel_launch(void* const* d_in, const int* in_sizes, int n_in,
                              void* d_out, int out_size)
{
    const float* qin = (const float*)d_in[0];
    const float* sin = (const float*)d_in[1];
    const float* Wq  = (const float*)d_in[2];
    const float* Wk  = (const float*)d_in[3];
    const float* Wv  = (const float*)d_in[4];
    const float* Ws  = (const float*)d_in[5];
    const float* Wh  = (const float*)d_in[6];
    float* out = (float*)d_out;

    float *Yq, *Yk, *Yv, *ktvT, *ktvs, *sumK, *dS, *dH, *cs, *atts, *bb;
    uint32_t *Xqh, *Xql, *Xsh, *Xsl, *Wqh, *Wql, *Wkh, *Wkl, *Wvh, *Wvl;
    uint32_t *Whh, *Whl, *chh, *chl, *ktph, *ktpl;
    cudaGetSymbolAddress((void**)&Yq,   g_Yq);
    cudaGetSymbolAddress((void**)&Yk,   g_Yk);
    cudaGetSymbolAddress((void**)&Yv,   g_Yv);
    cudaGetSymbolAddress((void**)&ktvT, g_ktvT);
    cudaGetSymbolAddress((void**)&ktvs, g_ktvs);
    cudaGetSymbolAddress((void**)&sumK, g_sumK);
    cudaGetSymbolAddress((void**)&dS,   g_denS);
    cudaGetSymbolAddress((void**)&dH,   g_denH);
    cudaGetSymbolAddress((void**)&cs,   g_cs);
    cudaGetSymbolAddress((void**)&atts, g_atts);
    cudaGetSymbolAddress((void**)&bb,   g_b);
    cudaGetSymbolAddress((void**)&Xqh,  g_Xq_hi); cudaGetSymbolAddress((void**)&Xql, g_Xq_lo);
    cudaGetSymbolAddress((void**)&Xsh,  g_Xs_hi); cudaGetSymbolAddress((void**)&Xsl, g_Xs_lo);
    cudaGetSymbolAddress((void**)&Wqh,  g_Wq_hi); cudaGetSymbolAddress((void**)&Wql, g_Wq_lo);
    cudaGetSymbolAddress((void**)&Wkh,  g_Wk_hi); cudaGetSymbolAddress((void**)&Wkl, g_Wk_lo);
    cudaGetSymbolAddress((void**)&Wvh,  g_Wv_hi); cudaGetSymbolAddress((void**)&Wvl, g_Wv_lo);
    cudaGetSymbolAddress((void**)&Whh,  g_Wh_hi); cudaGetSymbolAddress((void**)&Whl, g_Wh_lo);
    cudaGetSymbolAddress((void**)&chh,  g_ch_hi); cudaGetSymbolAddress((void**)&chl, g_ch_lo);
    cudaGetSymbolAddress((void**)&ktph, g_ktvp_hi); cudaGetSymbolAddress((void**)&ktpl, g_ktvp_lo);

    static int smem_set = 0;
    if (!smem_set) {
        cudaFuncSetAttribute(gemm_pp_db, cudaFuncAttributeMaxDynamicSharedMemorySize, 2 * STAGE_BYTES);
        smem_set = 1;
    }

    const int rowTiles = (NROWS + 127) / 128;   // 235
    const int fTiles   = (FF + 127) / 128;      // 17
    const int KPX      = 129;                   // pairs for K=257

    // packs: inputs + all weights
    pack_kernel<<<(NROWS * LDP + 255) / 256, 256>>>(qin, Xqh, Xql, NROWS, DD, DD, LDP);
    pack_kernel<<<(NROWS * LDP + 255) / 256, 256>>>(sin, Xsh, Xsl, NROWS, DD, DD, LDP);
    pack_kernel<<<(FF * LDP + 255) / 256, 256>>>(Wq, Wqh, Wql, FF, DD, DD, LDP);
    pack_kernel<<<(FF * LDP + 255) / 256, 256>>>(Wk, Wkh, Wkl, FF, DD, DD, LDP);
    pack_kernel<<<(FF * LDP + 255) / 256, 256>>>(Wv, Wvh, Wvl, FF, DD, DD, LDP);
    pack_kernel<<<(OSD * CHP + 255) / 256, 256>>>(Wh, Whh, Whl, OSD, HH * OSD, HH * OSD, CHP);

    // projections (packed operands, cp.async double buffer)
    gemm_pp_db<<<dim3(fTiles, rowTiles), 256, 2 * STAGE_BYTES>>>(
        Xqh, Xql, Wqh, Wql, Yq, NROWS, FF, KPX, LDP, LDP, FF, 1);
    gemm_pp_db<<<dim3(fTiles, rowTiles), 256, 2 * STAGE_BYTES>>>(
        Xsh, Xsl, Wkh, Wkl, Yk, NROWS, FF, KPX, LDP, LDP, FF, 1);
    gemm_pp_db<<<dim3(fTiles, rowTiles), 256, 2 * STAGE_BYTES>>>(
        Xsh, Xsl, Wvh, Wvl, Yv, NROWS, FF, KPX, LDP, LDP, FF, 0);

    // zero accumulators
    zero_kernel<<<(HH * DD * DD + 255) / 256, 256>>>(ktvT, HH * DD * DD);
    zero_kernel<<<(HH * SD * SD + 255) / 256, 256>>>(ktvs, HH * SD * SD);
    zero_kernel<<<(FF + 255) / 256, 256>>>(sumK, FF);

    // s-part normalize + phi
    ep1s_kernel<<<NROWS, 256>>>(Yq, 1);
    ep1s_kernel<<<NROWS, 256>>>(Yk, 1);
    ep1s_kernel<<<NROWS, 256>>>(Yv, 0);

    // sumK, h-block ktv, s-block ktv
    colsum_kernel<<<dim3((FF + 255) / 256, 40), 256>>>(Yk, sumK);
    ktv_bf16s_tn<<<dim3(2, 2, HH * KTV_NSPLIT), 256>>>(Yk, Yv, ktvT);
    ktvs_kernel<<<dim3(KTVS_NCHUNK, HH), 320>>>(Yk, Yv, ktvs);

    // pack ktvT for attn B-side
    ktvp_pack_kernel<<<(HH * OSD * KTP + 255) / 256, 256>>>(ktvT, ktph, ktpl);

    // denominators
    den_kernel<<<NROWS, 256>>>(Yq, sumK, dS, dH);

    // attention: s-part + h-part (packed B, packed ch output)
    cs_kernel<<<NROWS, 256>>>(Yq, ktvs, dS, cs);
    attn_gemm<<<dim3(2, rowTiles, HH), 256>>>(Yq, ktph, ktpl, dH, chh, chl);

    // small Ws GEMM + att_s normalize
    a_kernel<<<(NROWS + 7) / 8, 256>>>(cs, Ws, atts);

    // b = ch @ Wh^T  (fully packed, double-buffered)
    gemm_pp_db<<<dim3(2, rowTiles), 256, 2 * STAGE_BYTES>>>(
        chh, chl, Whh, Whl, bb, NROWS, OSD, CHP, CHP, CHP, OSD, 0);

    // final epilogue
    final_kernel<<<(NROWS + 7) / 8, 256>>>(bb, atts, out);
}

// round 12
// speedup vs baseline: 1.1028x; 1.1028x over previous
#include <cuda_runtime.h>
#include <cuda_bf16.h>
#include <stdint.h>
#include <math.h>

// Problem constants
#define NROWS 30000
#define HH    8
#define SD    17          // OT+1
#define OSD   240
#define DD    257         // IN_DIM == OUT_DIM
#define FF    2056        // H * 257
#define LDP   144         // padded pair-stride for packed X/W (16B-aligned rows)

// ---------------- scratch (device globals; no runtime alloc allowed) -------
__device__ float    g_Yq[NROWS * FF];
__device__ float    g_Yk[NROWS * FF];
__device__ float    g_Yv[NROWS * FF];
__device__ float    g_ktvT[HH * DD * DD];  // ktvT[h][d][m] (h-block only)
__device__ float    g_ktvs[HH * SD * SD];  // s-block ktv[h][m][d]
__device__ float    g_sumK[FF];
__device__ float    g_denS[NROWS * HH];
__device__ float    g_denH[NROWS * HH];
__device__ float    g_cs[NROWS * HH * SD];
__device__ float    g_ch[NROWS * HH * OSD];
__device__ float    g_atts[NROWS * SD];
__device__ float    g_b[NROWS * OSD];
// packed projection operands (hi/lo bf16x2)
__device__ uint32_t g_Xq_hi[NROWS * LDP], g_Xq_lo[NROWS * LDP];
__device__ uint32_t g_Xs_hi[NROWS * LDP], g_Xs_lo[NROWS * LDP];
__device__ uint32_t g_Wq_hi[FF * LDP],    g_Wq_lo[FF * LDP];
__device__ uint32_t g_Wk_hi[FF * LDP],    g_Wk_lo[FF * LDP];
__device__ uint32_t g_Wv_hi[FF * LDP],    g_Wv_lo[FF * LDP];

// ---------------------------------------------------------------------------
__device__ __forceinline__ void mma16816(float c[4], const uint32_t a[4], const uint32_t b0, const uint32_t b1)
{
    asm volatile(
        "mma.sync.aligned.m16n8k16.row.col.f32.bf16.bf16.f32 "
        "{%0,%1,%2,%3}, {%4,%5,%6,%7}, {%8,%9}, {%0,%1,%2,%3};\n"
        : "+f"(c[0]), "+f"(c[1]), "+f"(c[2]), "+f"(c[3])
        : "r"(a[0]), "r"(a[1]), "r"(a[2]), "r"(a[3]), "r"(b0), "r"(b1));
}

__device__ __forceinline__ void ldsm_x4(uint32_t& r0, uint32_t& r1, uint32_t& r2, uint32_t& r3, uint32_t addr)
{
    asm volatile("ldmatrix.sync.aligned.m8n8.x4.shared.b16 {%0,%1,%2,%3}, [%4];"
                 : "=r"(r0), "=r"(r1), "=r"(r2), "=r"(r3) : "r"(addr));
}

__device__ __forceinline__ uint32_t smem_addr(const void* p)
{
    return (uint32_t)__cvta_generic_to_shared(p);
}

__device__ __forceinline__ void cp_async16(uint32_t dst, const void* src, int src_bytes)
{
    asm volatile("cp.async.cg.shared.global [%0], [%1], 16, %2;"
                 :: "r"(dst), "l"(src), "r"(src_bytes));
}

__device__ __forceinline__ void cvt_pack(float x0, float x1, uint32_t& hp, uint32_t& lp)
{
    __nv_bfloat16 h0 = __float2bfloat16(x0);
    __nv_bfloat16 h1 = __float2bfloat16(x1);
    __nv_bfloat16 l0 = __float2bfloat16(x0 - __bfloat162float(h0));
    __nv_bfloat16 l1 = __float2bfloat16(x1 - __bfloat162float(h1));
    __nv_bfloat162 hh; hh.x = h0; hh.y = h1;
    __nv_bfloat162 ll; ll.x = l0; ll.y = l1;
    hp = *reinterpret_cast<uint32_t*>(&hh);
    lp = *reinterpret_cast<uint32_t*>(&ll);
}

// --------- pack fp32 matrix into bf16x2 hi/lo pair arrays (LDP-padded) -----
__global__ void pack_kernel(const float* __restrict__ src,
                            uint32_t* __restrict__ hi, uint32_t* __restrict__ lo,
                            int rows, int K, int ld)
{
    int idx = blockIdx.x * blockDim.x + threadIdx.x;
    if (idx >= rows * LDP) return;
    int r_ = idx / LDP, kp = idx - r_ * LDP;
    int k = kp * 2;
    float x0 = (k < K)     ? src[r_ * ld + k]     : 0.f;
    float x1 = (k + 1 < K) ? src[r_ * ld + k + 1] : 0.f;
    uint32_t hp, lp; cvt_pack(x0, x1, hp, lp);
    hi[idx] = hp; lo[idx] = lp;
}

// ---------------------------------------------------------------------------
// Projection GEMM: pre-packed operands + cp.async 2-stage double buffer.
// ---------------------------------------------------------------------------
#define STAGE_BYTES 40960
#define ARR_BYTES   10240
__global__ __launch_bounds__(256, 2) void gemm_pp_db(
    const uint32_t* __restrict__ Apk_h, const uint32_t* __restrict__ Apk_l,
    const uint32_t* __restrict__ Bpk_h, const uint32_t* __restrict__ Bpk_l,
    float* __restrict__ C,
    int M, int N, int KP, int ldc, int phiH)
{
    extern __shared__ char smem[];
    const uint32_t smem_u32 = smem_addr(smem);

    const int tid  = threadIdx.x;
    const int lane = tid & 31;
    const int wid  = tid >> 5;
    const int wm   = wid & 3;
    const int wn   = wid >> 2;
    const int row0 = blockIdx.y * 128;
    const int col0 = blockIdx.x * 128;
    const int r    = lane >> 2;
    const int q4   = lane & 3;

    const int aRow = (lane & 15);
    const int aCol = (lane >> 4) * 4;
    const int bRow = (lane & 7) + ((lane >> 4) << 3);
    const int bCol = ((lane >> 3) & 1) * 4;

    float acc[2][8][4];
#pragma unroll
    for (int mt = 0; mt < 2; mt++)
#pragma unroll
        for (int nt = 0; nt < 8; nt++)
#pragma unroll
            for (int i = 0; i < 4; i++) acc[mt][nt][i] = 0.f;

    const int KT = (KP + 15) >> 4;

    auto fill = [&](int kt, int s) {
        int kp0 = kt * 16;
        uint32_t stage = smem_u32 + s * STAGE_BYTES;
#pragma unroll
        for (int t = 0; t < 2; t++) {
            int ci  = tid + t * 256;
            int m   = ci >> 2;
            int cp4 = (ci & 3) * 4;
            uint32_t doff = (uint32_t)(m * 20 + cp4) * 4u;
            int gm = row0 + m;
            long aoff = (long)gm * LDP + kp0 + cp4;
            int szA = (gm < M) ? 16 : 0;
            cp_async16(stage + doff,                 Apk_h + aoff, szA);
            cp_async16(stage + ARR_BYTES + doff,     Apk_l + aoff, szA);
            int gn = col0 + m;
            long boff = (long)gn * LDP + kp0 + cp4;
            int szB = (gn < N) ? 16 : 0;
            cp_async16(stage + 2 * ARR_BYTES + doff, Bpk_h + boff, szB);
            cp_async16(stage + 3 * ARR_BYTES + doff, Bpk_l + boff, szB);
        }
    };

    fill(0, 0);
    asm volatile("cp.async.commit_group;");

    for (int kt = 0; kt < KT; kt++) {
        int s = kt & 1;
        if (kt + 1 < KT) {
            fill(kt + 1, (kt + 1) & 1);
            asm volatile("cp.async.commit_group;");
            asm volatile("cp.async.wait_group 1;");
        } else {
            asm volatile("cp.async.wait_group 0;");
        }
        __syncthreads();

        uint32_t baseAh = smem_u32 + s * STAGE_BYTES;
        uint32_t baseAl = baseAh + ARR_BYTES;
        uint32_t baseBh = baseAh + 2 * ARR_BYTES;
        uint32_t baseBl = baseAh + 3 * ARR_BYTES;

#pragma unroll
        for (int ks = 0; ks < 2; ks++) {
            uint32_t ah[2][4], al[2][4];
#pragma unroll
            for (int mt = 0; mt < 2; mt++) {
                uint32_t off = (uint32_t)((wm * 32 + mt * 16 + aRow) * 20 + ks * 8 + aCol) * 4u;
                ldsm_x4(ah[mt][0], ah[mt][1], ah[mt][2], ah[mt][3], baseAh + off);
                ldsm_x4(al[mt][0], al[mt][1], al[mt][2], al[mt][3], baseAl + off);
            }
#pragma unroll
            for (int ntp = 0; ntp < 4; ntp++) {
                uint32_t off = (uint32_t)((wn * 64 + ntp * 16 + bRow) * 20 + ks * 8 + bCol) * 4u;
                uint32_t bh[4], bl[4];
                ldsm_x4(bh[0], bh[1], bh[2], bh[3], baseBh + off);
                ldsm_x4(bl[0], bl[1], bl[2], bl[3], baseBl + off);
#pragma unroll
                for (int sub = 0; sub < 2; sub++) {
                    int nt = ntp * 2 + sub;
#pragma unroll
                    for (int mt = 0; mt < 2; mt++) {
                        mma16816(acc[mt][nt], ah[mt], bh[sub * 2], bh[sub * 2 + 1]);
                        mma16816(acc[mt][nt], al[mt], bh[sub * 2], bh[sub * 2 + 1]);
                        mma16816(acc[mt][nt], ah[mt], bl[sub * 2], bl[sub * 2 + 1]);
                    }
                }
            }
        }
        __syncthreads();
    }

#pragma unroll
    for (int mt = 0; mt < 2; mt++) {
        int rm0 = row0 + wm * 32 + mt * 16 + r;
        int rm1 = rm0 + 8;
#pragma unroll
        for (int nt = 0; nt < 8; nt++) {
            int cn = col0 + wn * 64 + nt * 8 + q4 * 2;
#pragma unroll
            for (int jj = 0; jj < 2; jj++) {
                int gn = cn + jj;
                if (gn >= N) continue;
                bool phi = phiH && (gn % DD) >= SD;
                if (rm0 < M) {
                    float v = acc[mt][nt][jj];
                    if (phi) v = (v > 0.f) ? v + 1.f : __expf(v);
                    C[rm0 * ldc + gn] = v;
                }
                if (rm1 < M) {
                    float v = acc[mt][nt][2 + jj];
                    if (phi) v = (v > 0.f) ? v + 1.f : __expf(v);
                    C[rm1 * ldc + gn] = v;
                }
            }
        }
    }
}

// ---------------------------------------------------------------------------
// Generic NT tensor-core GEMM (in-loop cvt; used for attn + Wh).
// epi==0: plain store. epi==1: h-part attention scatter (divide by dH -> ch).
// ---------------------------------------------------------------------------
__global__ __launch_bounds__(256, 2) void gemm_bf16s_nt(
    const float* __restrict__ A, const float* __restrict__ B, float* __restrict__ C,
    int M, int N, int K, int lda, int ldb, int ldc,
    int strideAz, int strideBz, int strideCz,
    int epi,
    const float* __restrict__ dH,
    float* __restrict__ ch,
    int phiH)
{
    __shared__ uint32_t Ah[128][20], Al[128][20], Bh[128][20], Bl[128][20];

    const int z = blockIdx.z;
    A += (long)z * strideAz;
    B += (long)z * strideBz;
    if (epi == 0) C += (long)z * strideCz;

    const int tid  = threadIdx.x;
    const int lane = tid & 31;
    const int wid  = tid >> 5;
    const int wm   = wid & 3;
    const int wn   = wid >> 2;
    const int row0 = blockIdx.y * 128;
    const int col0 = blockIdx.x * 128;
    const int r    = lane >> 2;
    const int q4   = lane & 3;

    const int aRow = (lane & 15);
    const int aCol = (lane >> 4) * 4;
    const int bRow = (lane & 7) + ((lane >> 4) << 3);
    const int bCol = ((lane >> 3) & 1) * 4;

    float acc[2][8][4];
#pragma unroll
    for (int mt = 0; mt < 2; mt++)
#pragma unroll
        for (int nt = 0; nt < 8; nt++)
#pragma unroll
            for (int i = 0; i < 4; i++) acc[mt][nt][i] = 0.f;

    for (int k0 = 0; k0 < K; k0 += 32) {
#pragma unroll
        for (int i = 0; i < 8; i++) {
            int idx = tid + i * 256;
            int m = idx >> 4, kp = idx & 15;
            int gm = row0 + m, gk = k0 + kp * 2;
            float x0 = (gm < M && gk     < K) ? __ldg(&A[gm * lda + gk])     : 0.f;
            float x1 = (gm < M && gk + 1 < K) ? __ldg(&A[gm * lda + gk + 1]) : 0.f;
            uint32_t hp, lp; cvt_pack(x0, x1, hp, lp);
            Ah[m][kp] = hp; Al[m][kp] = lp;
        }
#pragma unroll
        for (int i = 0; i < 8; i++) {
            int idx = tid + i * 256;
            int n = idx >> 4, kp = idx & 15;
            int gn = col0 + n, gk = k0 + kp * 2;
            float x0 = (gn < N && gk     < K) ? __ldg(&B[gn * ldb + gk])     : 0.f;
            float x1 = (gn < N && gk + 1 < K) ? __ldg(&B[gn * ldb + gk + 1]) : 0.f;
            uint32_t hp, lp; cvt_pack(x0, x1, hp, lp);
            Bh[n][kp] = hp; Bl[n][kp] = lp;
        }
        __syncthreads();

#pragma unroll
        for (int ks = 0; ks < 2; ks++) {
            uint32_t ah[2][4], al[2][4];
#pragma unroll
            for (int mt = 0; mt < 2; mt++) {
                int m_ = wm * 32 + mt * 16 + aRow;
                int c_ = ks * 8 + aCol;
                ldsm_x4(ah[mt][0], ah[mt][1], ah[mt][2], ah[mt][3], smem_addr(&Ah[m_][c_]));
                ldsm_x4(al[mt][0], al[mt][1], al[mt][2], al[mt][3], smem_addr(&Al[m_][c_]));
            }
#pragma unroll
            for (int ntp = 0; ntp < 4; ntp++) {
                int n_ = wn * 64 + ntp * 16 + bRow;
                int c_ = ks * 8 + bCol;
                uint32_t bh[4], bl[4];
                ldsm_x4(bh[0], bh[1], bh[2], bh[3], smem_addr(&Bh[n_][c_]));
                ldsm_x4(bl[0], bl[1], bl[2], bl[3], smem_addr(&Bl[n_][c_]));
#pragma unroll
                for (int sub = 0; sub < 2; sub++) {
                    int nt = ntp * 2 + sub;
#pragma unroll
                    for (int mt = 0; mt < 2; mt++) {
                        mma16816(acc[mt][nt], ah[mt], bh[sub * 2], bh[sub * 2 + 1]);
                        mma16816(acc[mt][nt], al[mt], bh[sub * 2], bh[sub * 2 + 1]);
                        mma16816(acc[mt][nt], ah[mt], bl[sub * 2], bl[sub * 2 + 1]);
                    }
                }
            }
        }
        __syncthreads();
    }

    if (epi == 0) {
#pragma unroll
        for (int mt = 0; mt < 2; mt++) {
            int rm0 = row0 + wm * 32 + mt * 16 + r;
            int rm1 = rm0 + 8;
#pragma unroll
            for (int nt = 0; nt < 8; nt++) {
                int cn = col0 + wn * 64 + nt * 8 + q4 * 2;
#pragma unroll
                for (int jj = 0; jj < 2; jj++) {
                    int gn = cn + jj;
                    if (gn >= N) continue;
                    bool phi = phiH && (gn % DD) >= SD;
                    if (rm0 < M) {
                        float v = acc[mt][nt][jj];
                        if (phi) v = (v > 0.f) ? v + 1.f : __expf(v);
                        C[rm0 * ldc + gn] = v;
                    }
                    if (rm1 < M) {
                        float v = acc[mt][nt][2 + jj];
                        if (phi) v = (v > 0.f) ? v + 1.f : __expf(v);
                        C[rm1 * ldc + gn] = v;
                    }
                }
            }
        }
    } else {
        int h = z;
#pragma unroll
        for (int mt = 0; mt < 2; mt++) {
            int rm0 = row0 + wm * 32 + mt * 16 + r;
            int rm1 = rm0 + 8;
            float dh0 = 1.f, dh1 = 1.f;
            if (rm0 < M) dh0 = dH[rm0 * HH + h] + 1e-8f;
            if (rm1 < M) dh1 = dH[rm1 * HH + h] + 1e-8f;
#pragma unroll
            for (int nt = 0; nt < 8; nt++) {
                int cn = col0 + wn * 64 + nt * 8 + q4 * 2;
#pragma unroll
                for (int jj = 0; jj < 2; jj++) {
                    int d = cn + jj;
                    if (d >= OSD) continue;
                    if (rm0 < M) ch[rm0 * (HH * OSD) + h * OSD + d] = acc[mt][nt][jj]     / dh0;
                    if (rm1 < M) ch[rm1 * (HH * OSD) + h * OSD + d] = acc[mt][nt][2 + jj] / dh1;
                }
            }
        }
    }
}

// ---------------------------------------------------------------------------
// ktv h-block (TN): ktvT[h][d+SD][m+SD] = sum_n phiKh[n,m] * Vh[n,d]
// ---------------------------------------------------------------------------
#define KTV_NSPLIT 20
__global__ __launch_bounds__(256, 2) void ktv_bf16s_tn(
    const float* __restrict__ Yk, const float* __restrict__ Yv,
    float* __restrict__ ktvT)
{
    __shared__ uint32_t Ah[128][20], Al[128][20], Bh[128][20], Bl[128][20];

    const int h  = blockIdx.z / KTV_NSPLIT;
    const int sp = blockIdx.z % KTV_NSPLIT;
    const int m0 = blockIdx.x * 128;
    const int d0 = blockIdx.y * 128;
    const int chunk = (NROWS + KTV_NSPLIT - 1) / KTV_NSPLIT;
    const int n0 = sp * chunk;
    int n1 = n0 + chunk; if (n1 > NROWS) n1 = NROWS;

    const float* Kp = Yk + h * DD + SD;
    const float* Vp = Yv + h * DD + SD;

    const int tid  = threadIdx.x;
    const int lane = tid & 31;
    const int wid  = tid >> 5;
    const int wm   = wid & 3;
    const int wn   = wid >> 2;
    const int r    = lane >> 2;
    const int q4   = lane & 3;

    const int aRow = (lane & 15);
    const int aCol = (lane >> 4) * 4;
    const int bRow = (lane & 7) + ((lane >> 4) << 3);
    const int bCol = ((lane >> 3) & 1) * 4;

    float acc[2][8][4];
#pragma unroll
    for (int mt = 0; mt < 2; mt++)
#pragma unroll
        for (int nt = 0; nt < 8; nt++)
#pragma unroll
            for (int i = 0; i < 4; i++) acc[mt][nt][i] = 0.f;

    for (int kb = n0; kb < n1; kb += 32) {
#pragma unroll
        for (int i = 0; i < 8; i++) {
            int idx = tid + i * 256;
            int m = idx & 127, np = idx >> 7;
            int gm = m0 + m;
            int gn = kb + np * 2;
            bool mok = (gm < OSD);
            float x0 = (mok && gn     < n1) ? __ldg(&Kp[gn * FF + gm])       : 0.f;
            float x1 = (mok && gn + 1 < n1) ? __ldg(&Kp[(gn + 1) * FF + gm]) : 0.f;
            uint32_t hp, lp; cvt_pack(x0, x1, hp, lp);
            Ah[m][np] = hp; Al[m][np] = lp;
        }
#pragma unroll
        for (int i = 0; i < 8; i++) {
            int idx = tid + i * 256;
            int d = idx & 127, np = idx >> 7;
            int gd = d0 + d;
            int gn = kb + np * 2;
            bool dok = (gd < OSD);
            float x0 = (dok && gn     < n1) ? __ldg(&Vp[gn * FF + gd])       : 0.f;
            float x1 = (dok && gn + 1 < n1) ? __ldg(&Vp[(gn + 1) * FF + gd]) : 0.f;
            uint32_t hp, lp; cvt_pack(x0, x1, hp, lp);
            Bh[d][np] = hp; Bl[d][np] = lp;
        }
        __syncthreads();

#pragma unroll
        for (int ks = 0; ks < 2; ks++) {
            uint32_t ah[2][4], al[2][4];
#pragma unroll
            for (int mt = 0; mt < 2; mt++) {
                int m_ = wm * 32 + mt * 16 + aRow;
                int c_ = ks * 8 + aCol;
                ldsm_x4(ah[mt][0], ah[mt][1], ah[mt][2], ah[mt][3], smem_addr(&Ah[m_][c_]));
                ldsm_x4(al[mt][0], al[mt][1], al[mt][2], al[mt][3], smem_addr(&Al[m_][c_]));
            }
#pragma unroll
            for (int ntp = 0; ntp < 4; ntp++) {
                int n_ = wn * 64 + ntp * 16 + bRow;
                int c_ = ks * 8 + bCol;
                uint32_t bh[4], bl[4];
                ldsm_x4(bh[0], bh[1], bh[2], bh[3], smem_addr(&Bh[n_][c_]));
                ldsm_x4(bl[0], bl[1], bl[2], bl[3], smem_addr(&Bl[n_][c_]));
#pragma unroll
                for (int sub = 0; sub < 2; sub++) {
                    int nt = ntp * 2 + sub;
#pragma unroll
                    for (int mt = 0; mt < 2; mt++) {
                        mma16816(acc[mt][nt], ah[mt], bh[sub * 2], bh[sub * 2 + 1]);
                        mma16816(acc[mt][nt], al[mt], bh[sub * 2], bh[sub * 2 + 1]);
                        mma16816(acc[mt][nt], ah[mt], bl[sub * 2], bl[sub * 2 + 1]);
                    }
                }
            }
        }
        __syncthreads();
    }

    float* kt = ktvT + h * DD * DD;
#pragma unroll
    for (int mt = 0; mt < 2; mt++) {
        int gm0 = m0 + wm * 32 + mt * 16 + r;
        int gm1 = gm0 + 8;
#pragma unroll
        for (int nt = 0; nt < 8; nt++) {
            int gd = d0 + wn * 64 + nt * 8 + q4 * 2;
#pragma unroll
            for (int jj = 0; jj < 2; jj++) {
                int d = gd + jj;
                if (d >= OSD) continue;
                if (gm0 < OSD) atomicAdd(&kt[(d + SD) * DD + (gm0 + SD)], acc[mt][nt][jj]);
                if (gm1 < OSD) atomicAdd(&kt[(d + SD) * DD + (gm1 + SD)], acc[mt][nt][2 + jj]);
            }
        }
    }
}

// --------- s-block ktv ------------------------------------------------------
#define KTVS_NCHUNK 100
__global__ __launch_bounds__(320) void ktvs_kernel(
    const float* __restrict__ Yk, const float* __restrict__ Yv,
    float* __restrict__ ktvs)
{
    __shared__ float sk[SD], sv[SD];
    int h  = blockIdx.y;
    int cn = blockIdx.x;
    int chunk = (NROWS + KTVS_NCHUNK - 1) / KTVS_NCHUNK;
    int n0 = cn * chunk;
    int n1 = n0 + chunk; if (n1 > NROWS) n1 = NROWS;
    int t = threadIdx.x;
    int m = t / SD, d = t - m * SD;
    bool act = (t < SD * SD);
    float acc = 0.f;
    for (int n = n0; n < n1; n++) {
        if (t < SD)            sk[t]      = Yk[n * FF + h * DD + t];
        else if (t < 2 * SD)   sv[t - SD] = Yv[n * FF + h * DD + (t - SD)];
        __syncthreads();
        if (act) acc += sk[m] * sv[d];
        __syncthreads();
    }
    if (act) atomicAdd(&ktvs[h * SD * SD + m * SD + d], acc);
}

// --------- s-part attention fused: cs = (phiQs @ ktvs) / denS --------------
__global__ void cs_kernel(const float* __restrict__ Yq,
                          const float* __restrict__ ktvs,
                          const float* __restrict__ dS,
                          float* __restrict__ cs)
{
    int warp = (blockIdx.x * blockDim.x + threadIdx.x) >> 5;
    int lane = threadIdx.x & 31;
    if (warp >= NROWS * HH) return;
    int n = warp / HH, h = warp - n * HH;
    const float* q = Yq + n * FF + h * DD;
    const float* kt = ktvs + h * SD * SD;
    float qv = (lane < SD) ? q[lane] : 0.f;
    float acc = 0.f;
#pragma unroll
    for (int m = 0; m < SD; m++) {
        float qm = __shfl_sync(0xffffffffu, qv, m);
        if (lane < SD) acc += qm * kt[m * SD + lane];
    }
    if (lane < SD) cs[n * (HH * SD) + h * SD + lane] = acc / (dS[n * HH + h] + 1e-6f);
}

// --------- s-part pseudo-linear fixup --------------------------------------
__global__ void ep1s_kernel(float* __restrict__ Y, int do_phi)
{
    int warp = (blockIdx.x * blockDim.x + threadIdx.x) >> 5;
    int lane = threadIdx.x & 31;
    if (warp >= NROWS * HH) return;
    int n = warp / HH, h = warp - n * HH;
    float* p = Y + n * FF + h * DD;
    float x = (lane < SD) ? p[lane] : 0.f;
    float ss = x * x;
#pragma unroll
    for (int o = 16; o > 0; o >>= 1) ss += __shfl_xor_sync(0xffffffffu, ss, o);
    float scale = 1.f / (sqrtf(ss) + 1e-8f);
    if (lane < SD) {
        float y = x * scale;
        if (do_phi) y = (y > 0.f) ? y + 1.f : __expf(y);
        p[lane] = y;
    }
}

__global__ void zero_kernel(float* __restrict__ p, int n)
{
    int i = blockIdx.x * blockDim.x + threadIdx.x;
    if (i < n) p[i] = 0.f;
}

// --------- column sums of phiK ---------------------------------------------
__global__ void colsum_kernel(const float* __restrict__ Y, float* __restrict__ out)
{
    int f = blockIdx.x * blockDim.x + threadIdx.x;
    if (f >= FF) return;
    int n0 = blockIdx.y * 750;
    int n1 = n0 + 750; if (n1 > NROWS) n1 = NROWS;
    float s = 0.f;
    for (int n = n0; n < n1; n++) s += Y[n * FF + f];
    atomicAdd(&out[f], s);
}

// --------- den_s / den_h per (n,h) -----------------------------------------
__global__ void den_kernel(const float* __restrict__ PQ,
                           const float* __restrict__ sumK,
                           float* __restrict__ dS, float* __restrict__ dH)
{
    int n = blockIdx.x;
    int h = threadIdx.x >> 5;
    int lane = threadIdx.x & 31;
    const float* p = PQ + n * FF + h * DD;
    const float* s = sumK + h * DD;
    float as = 0.f, ah = 0.f;
    for (int m = lane; m < DD; m += 32) {
        float v = p[m] * s[m];
        if (m < SD) as += v; else ah += v;
    }
#pragma unroll
    for (int o = 16; o > 0; o >>= 1) {
        as += __shfl_xor_sync(0xffffffffu, as, o);
        ah += __shfl_xor_sync(0xffffffffu, ah, o);
    }
    if (lane == 0) { dS[n * HH + h] = as; dH[n * HH + h] = ah; }
}

// --------- a = c_s @ Ws^T, att_s = a / max(||a||,1e-12) --------------------
__global__ void a_kernel(const float* __restrict__ cs,
                         const float* __restrict__ Ws,
                         float* __restrict__ atts)
{
    __shared__ float ws[SD * 136];
    for (int i = threadIdx.x; i < SD * 136; i += blockDim.x) ws[i] = Ws[i];
    __syncthreads();
    int warp = threadIdx.x >> 5, lane = threadIdx.x & 31;
    int n = blockIdx.x * 8 + warp;
    if (n >= NROWS) return;
    float acc[SD];
#pragma unroll
    for (int o = 0; o < SD; o++) acc[o] = 0.f;
    for (int f = lane; f < 136; f += 32) {
        float x = cs[n * 136 + f];
#pragma unroll
        for (int o = 0; o < SD; o++) acc[o] += x * ws[o * 136 + f];
    }
#pragma unroll
    for (int o = 0; o < SD; o++)
#pragma unroll
        for (int s = 16; s > 0; s >>= 1)
            acc[o] += __shfl_xor_sync(0xffffffffu, acc[o], s);
    if (lane == 0) {
        float ss = 0.f;
#pragma unroll
        for (int o = 0; o < SD; o++) ss += acc[o] * acc[o];
        float sc = 1.f / fmaxf(sqrtf(ss), 1e-12f);
#pragma unroll
        for (int o = 0; o < SD; o++) atts[n * SD + o] = acc[o] * sc;
    }
}

// --------- final epilogue ---------------------------------------------------
__global__ void final_kernel(const float* __restrict__ b,
                             const float* __restrict__ atts,
                             float* __restrict__ out)
{
    int warp = threadIdx.x >> 5, lane = threadIdx.x & 31;
    int n = blockIdx.x * 8 + warp;
    if (n >= NROWS) return;
    const float* br = b + n * OSD;
    float ss = 0.f;
    for (int j = lane; j < OSD; j += 32) { float v = br[j]; ss += v * v; }
#pragma unroll
    for (int s = 16; s > 0; s >>= 1) ss += __shfl_xor_sync(0xffffffffu, ss, s);
    float nr  = sqrtf(ss);
    float bn  = nr + 1e-8f;
    float bnc = fminf(bn, 1e6f);
    float bt  = sqrtf(bnc * bnc + 1.0f);
    float scale = (bn > 1e6f) ? (1e6f / fmaxf(nr, 1e-12f * bnc)) : 1.0f;
    float* o = out + n * DD;
    for (int j = lane; j < OSD; j += 32) o[SD + j] = br[j] * scale;
    if (lane < SD) o[lane] = bt * atts[n * SD + lane];
}

// ---------------------------------------------------------------------------
extern "C" void kernel_launch(void* const* d_in, const int* in_sizes, int n_in,
                              void* d_out, int out_size)
{
    const float* qin = (const float*)d_in[0];
    const float* sin = (const float*)d_in[1];
    const float* Wq  = (const float*)d_in[2];
    const float* Wk  = (const float*)d_in[3];
    const float* Wv  = (const float*)d_in[4];
    const float* Ws  = (const float*)d_in[5];
    const float* Wh  = (const float*)d_in[6];
    float* out = (float*)d_out;

    float *Yq, *Yk, *Yv, *ktvT, *ktvs, *sumK, *dS, *dH, *cs, *ch, *atts, *bb;
    uint32_t *Xqh, *Xql, *Xsh, *Xsl, *Wqh, *Wql, *Wkh, *Wkl, *Wvh, *Wvl;
    cudaGetSymbolAddress((void**)&Yq,   g_Yq);
    cudaGetSymbolAddress((void**)&Yk,   g_Yk);
    cudaGetSymbolAddress((void**)&Yv,   g_Yv);
    cudaGetSymbolAddress((void**)&ktvT, g_ktvT);
    cudaGetSymbolAddress((void**)&ktvs, g_ktvs);
    cudaGetSymbolAddress((void**)&sumK, g_sumK);
    cudaGetSymbolAddress((void**)&dS,   g_denS);
    cudaGetSymbolAddress((void**)&dH,   g_denH);
    cudaGetSymbolAddress((void**)&cs,   g_cs);
    cudaGetSymbolAddress((void**)&ch,   g_ch);
    cudaGetSymbolAddress((void**)&atts, g_atts);
    cudaGetSymbolAddress((void**)&bb,   g_b);
    cudaGetSymbolAddress((void**)&Xqh,  g_Xq_hi); cudaGetSymbolAddress((void**)&Xql, g_Xq_lo);
    cudaGetSymbolAddress((void**)&Xsh,  g_Xs_hi); cudaGetSymbolAddress((void**)&Xsl, g_Xs_lo);
    cudaGetSymbolAddress((void**)&Wqh,  g_Wq_hi); cudaGetSymbolAddress((void**)&Wql, g_Wq_lo);
    cudaGetSymbolAddress((void**)&Wkh,  g_Wk_hi); cudaGetSymbolAddress((void**)&Wkl, g_Wk_lo);
    cudaGetSymbolAddress((void**)&Wvh,  g_Wv_hi); cudaGetSymbolAddress((void**)&Wvl, g_Wv_lo);

    // one-time setup (runs on the uncaptured correctness call first)
    static int inited = 0;
    static cudaStream_t sB;
    static cudaEvent_t eFork, eZero, eProjK, eProjV, eDen, eA;
    if (!inited) {
        cudaFuncSetAttribute(gemm_pp_db, cudaFuncAttributeMaxDynamicSharedMemorySize, 2 * STAGE_BYTES);
        cudaStreamCreateWithFlags(&sB, cudaStreamNonBlocking);
        cudaEventCreateWithFlags(&eFork,  cudaEventDisableTiming);
        cudaEventCreateWithFlags(&eZero,  cudaEventDisableTiming);
        cudaEventCreateWithFlags(&eProjK, cudaEventDisableTiming);
        cudaEventCreateWithFlags(&eProjV, cudaEventDisableTiming);
        cudaEventCreateWithFlags(&eDen,   cudaEventDisableTiming);
        cudaEventCreateWithFlags(&eA,     cudaEventDisableTiming);
        inited = 1;
    }

    const int rowTiles = (NROWS + 127) / 128;   // 235
    const int fTiles   = (FF + 127) / 128;      // 17
    const int KPX      = 129;                   // pairs for K=257

    // ---- fork stream B off stream 0 ----
    cudaEventRecord(eFork, 0);
    cudaStreamWaitEvent(sB, eFork, 0);

    // stream 0: packs needed by projK / projV
    pack_kernel<<<(NROWS * LDP + 255) / 256, 256, 0, 0>>>(sin, Xsh, Xsl, NROWS, DD, DD);
    pack_kernel<<<(FF * LDP + 255) / 256, 256, 0, 0>>>(Wk, Wkh, Wkl, FF, DD, DD);
    pack_kernel<<<(FF * LDP + 255) / 256, 256, 0, 0>>>(Wv, Wvh, Wvl, FF, DD, DD);

    // stream B: packs for projQ + zero accumulators
    pack_kernel<<<(NROWS * LDP + 255) / 256, 256, 0, sB>>>(qin, Xqh, Xql, NROWS, DD, DD);
    pack_kernel<<<(FF * LDP + 255) / 256, 256, 0, sB>>>(Wq, Wqh, Wql, FF, DD, DD);
    zero_kernel<<<(HH * DD * DD + 255) / 256, 256, 0, sB>>>(ktvT, HH * DD * DD);
    zero_kernel<<<(HH * SD * SD + 255) / 256, 256, 0, sB>>>(ktvs, HH * SD * SD);
    zero_kernel<<<(FF + 255) / 256, 256, 0, sB>>>(sumK, FF);
    cudaEventRecord(eZero, sB);

    // stream 0: projK, projV (backbone)
    gemm_pp_db<<<dim3(fTiles, rowTiles), 256, 2 * STAGE_BYTES, 0>>>(
        Xsh, Xsl, Wkh, Wkl, Yk, NROWS, FF, KPX, FF, 1);
    cudaEventRecord(eProjK, 0);
    gemm_pp_db<<<dim3(fTiles, rowTiles), 256, 2 * STAGE_BYTES, 0>>>(
        Xsh, Xsl, Wvh, Wvl, Yv, NROWS, FF, KPX, FF, 0);
    cudaEventRecord(eProjV, 0);

    // stream B: projQ + its s-part fixup (concurrent with stream 0 GEMMs)
    gemm_pp_db<<<dim3(fTiles, rowTiles), 256, 2 * STAGE_BYTES, sB>>>(
        Xqh, Xql, Wqh, Wql, Yq, NROWS, FF, KPX, FF, 1);
    ep1s_kernel<<<NROWS, 256, 0, sB>>>(Yq, 1);

    // stream 0: ktv (reads h-part only; doesn't need ep1s) after zeros
    cudaStreamWaitEvent(0, eZero, 0);
    ktv_bf16s_tn<<<dim3(2, 2, HH * KTV_NSPLIT), 256, 0, 0>>>(Yk, Yv, ktvT);

    // stream B: s-chain (overlaps ktv on stream 0)
    cudaStreamWaitEvent(sB, eProjK, 0);
    ep1s_kernel<<<NROWS, 256, 0, sB>>>(Yk, 1);
    colsum_kernel<<<dim3((FF + 255) / 256, 40), 256, 0, sB>>>(Yk, sumK);
    cudaStreamWaitEvent(sB, eProjV, 0);
    ep1s_kernel<<<NROWS, 256, 0, sB>>>(Yv, 0);
    ktvs_kernel<<<dim3(KTVS_NCHUNK, HH), 320, 0, sB>>>(Yk, Yv, ktvs);
    den_kernel<<<NROWS, 256, 0, sB>>>(Yq, sumK, dS, dH);
    cudaEventRecord(eDen, sB);
    cs_kernel<<<NROWS, 256, 0, sB>>>(Yq, ktvs, dS, cs);
    a_kernel<<<(NROWS + 7) / 8, 256, 0, sB>>>(cs, Ws, atts);
    cudaEventRecord(eA, sB);

    // stream 0: attention h-part (needs ktv on 0 + dH from B)
    cudaStreamWaitEvent(0, eDen, 0);
    gemm_bf16s_nt<<<dim3(2, rowTiles, HH), 256, 0, 0>>>(
        Yq + SD, ktvT + SD * DD + SD, nullptr, NROWS, OSD, OSD, FF, DD, 0,
        DD, DD * DD, 0, 1, dH, ch, 0);

    // stream 0: b = c_h @ Wh^T
    gemm_bf16s_nt<<<dim3(2, rowTiles, 1), 256, 0, 0>>>(
        ch, Wh, bb, NROWS, OSD, HH * OSD, HH * OSD, HH * OSD, OSD,
        0, 0, 0, 0, nullptr, nullptr, 0);

    // stream 0: final epilogue (join stream B)
    cudaStreamWaitEvent(0, eA, 0);
    final_kernel<<<(NROWS + 7) / 8, 256, 0, 0>>>(bb, atts, out);
}

// round 13
// speedup vs baseline: 1.2280x; 1.1135x over previous
#include <cuda_runtime.h>
#include <cuda_bf16.h>
#include <stdint.h>
#include <math.h>

// Problem constants
#define NROWS 30000
#define HH    8
#define SD    17          // OT+1
#define OSD   240
#define DD    257         // IN_DIM == OUT_DIM
#define FF    2056        // H * 257
#define LDP   144         // padded pair-stride for packed X/W (16B-aligned rows)
#define CHP   960         // pair-stride for packed Mb (K=1920)

// ---------------- scratch (device globals; no runtime alloc allowed) -------
__device__ float    g_Yq[NROWS * FF];
__device__ float    g_Yk[NROWS * FF];
__device__ float    g_Yv[NROWS * FF];
__device__ float    g_ktvT[HH * DD * DD];  // ktvT[h][d][m] (h-block only)
__device__ float    g_ktvs[HH * SD * SD];  // s-block ktv[h][m][d]
__device__ float    g_sumK[FF];
__device__ float    g_denS[NROWS * HH];
__device__ float    g_invDH[NROWS * HH];   // 1/(denH + 1e-8)
__device__ float    g_cs[NROWS * HH * SD];
__device__ float    g_atts[NROWS * SD];
__device__ float    g_b[NROWS * OSD];
__device__ float    g_Mb[OSD * HH * OSD];  // Mb[o][h*240+m] = M_h[m,o]
// packed operands (hi/lo bf16x2)
__device__ uint32_t g_Xq_hi[NROWS * LDP], g_Xq_lo[NROWS * LDP];
__device__ uint32_t g_Xs_hi[NROWS * LDP], g_Xs_lo[NROWS * LDP];
__device__ uint32_t g_Wq_hi[FF * LDP],    g_Wq_lo[FF * LDP];
__device__ uint32_t g_Wk_hi[FF * LDP],    g_Wk_lo[FF * LDP];
__device__ uint32_t g_Wv_hi[FF * LDP],    g_Wv_lo[FF * LDP];
__device__ uint32_t g_Mb_hi[OSD * CHP],   g_Mb_lo[OSD * CHP];

// ---------------------------------------------------------------------------
__device__ __forceinline__ void mma16816(float c[4], const uint32_t a[4], const uint32_t b0, const uint32_t b1)
{
    asm volatile(
        "mma.sync.aligned.m16n8k16.row.col.f32.bf16.bf16.f32 "
        "{%0,%1,%2,%3}, {%4,%5,%6,%7}, {%8,%9}, {%0,%1,%2,%3};\n"
        : "+f"(c[0]), "+f"(c[1]), "+f"(c[2]), "+f"(c[3])
        : "r"(a[0]), "r"(a[1]), "r"(a[2]), "r"(a[3]), "r"(b0), "r"(b1));
}

__device__ __forceinline__ void ldsm_x4(uint32_t& r0, uint32_t& r1, uint32_t& r2, uint32_t& r3, uint32_t addr)
{
    asm volatile("ldmatrix.sync.aligned.m8n8.x4.shared.b16 {%0,%1,%2,%3}, [%4];"
                 : "=r"(r0), "=r"(r1), "=r"(r2), "=r"(r3) : "r"(addr));
}

__device__ __forceinline__ uint32_t smem_addr(const void* p)
{
    return (uint32_t)__cvta_generic_to_shared(p);
}

__device__ __forceinline__ void cp_async16(uint32_t dst, const void* src, int src_bytes)
{
    asm volatile("cp.async.cg.shared.global [%0], [%1], 16, %2;"
                 :: "r"(dst), "l"(src), "r"(src_bytes));
}

__device__ __forceinline__ void cvt_pack(float x0, float x1, uint32_t& hp, uint32_t& lp)
{
    __nv_bfloat16 h0 = __float2bfloat16(x0);
    __nv_bfloat16 h1 = __float2bfloat16(x1);
    __nv_bfloat16 l0 = __float2bfloat16(x0 - __bfloat162float(h0));
    __nv_bfloat16 l1 = __float2bfloat16(x1 - __bfloat162float(h1));
    __nv_bfloat162 hh; hh.x = h0; hh.y = h1;
    __nv_bfloat162 ll; ll.x = l0; ll.y = l1;
    hp = *reinterpret_cast<uint32_t*>(&hh);
    lp = *reinterpret_cast<uint32_t*>(&ll);
}

// --------- pack fp32 matrix into bf16x2 hi/lo pair arrays ------------------
__global__ void pack_kernel(const float* __restrict__ src,
                            uint32_t* __restrict__ hi, uint32_t* __restrict__ lo,
                            int rows, int K, int ld, int ldp)
{
    int idx = blockIdx.x * blockDim.x + threadIdx.x;
    if (idx >= rows * ldp) return;
    int r_ = idx / ldp, kp = idx - r_ * ldp;
    int k = kp * 2;
    float x0 = (k < K)     ? src[r_ * ld + k]     : 0.f;
    float x1 = (k + 1 < K) ? src[r_ * ld + k + 1] : 0.f;
    uint32_t hp, lp; cvt_pack(x0, x1, hp, lp);
    hi[idx] = hp; lo[idx] = lp;
}

// ---------------------------------------------------------------------------
// Mb[o][h*240+m] = M_h[m,o] = sum_d ktvT_h[d][m] * Wh[o, h*240+d]   (fp32)
// ---------------------------------------------------------------------------
__global__ __launch_bounds__(256) void mh_kernel(
    const float* __restrict__ ktvT, const float* __restrict__ Wh,
    float* __restrict__ Mb)
{
    __shared__ float At[16][17], Bt[16][17];
    int h  = blockIdx.z;
    int m0 = blockIdx.x * 16;
    int o0 = blockIdx.y * 16;
    int tx = threadIdx.x & 15, ty = threadIdx.x >> 4;
    const float* kt = ktvT + h * DD * DD;
    float acc = 0.f;
    for (int d0 = 0; d0 < OSD; d0 += 16) {
        At[ty][tx] = kt[(d0 + ty + SD) * DD + (m0 + tx + SD)];
        Bt[ty][tx] = Wh[(o0 + tx) * (HH * OSD) + h * OSD + d0 + ty];
        __syncthreads();
#pragma unroll
        for (int dd = 0; dd < 16; dd++) acc += At[dd][tx] * Bt[dd][ty];
        __syncthreads();
    }
    Mb[(o0 + ty) * (HH * OSD) + h * OSD + m0 + tx] = acc;
}

// ---------------------------------------------------------------------------
// Projection GEMM: pre-packed operands + cp.async 2-stage double buffer.
// ---------------------------------------------------------------------------
#define STAGE_BYTES 40960
#define ARR_BYTES   10240
__global__ __launch_bounds__(256, 2) void gemm_pp_db(
    const uint32_t* __restrict__ Apk_h, const uint32_t* __restrict__ Apk_l,
    const uint32_t* __restrict__ Bpk_h, const uint32_t* __restrict__ Bpk_l,
    float* __restrict__ C,
    int M, int N, int KP, int ldc, int phiH)
{
    extern __shared__ char smem[];
    const uint32_t smem_u32 = smem_addr(smem);

    const int tid  = threadIdx.x;
    const int lane = tid & 31;
    const int wid  = tid >> 5;
    const int wm   = wid & 3;
    const int wn   = wid >> 2;
    const int row0 = blockIdx.y * 128;
    const int col0 = blockIdx.x * 128;
    const int r    = lane >> 2;
    const int q4   = lane & 3;

    const int aRow = (lane & 15);
    const int aCol = (lane >> 4) * 4;
    const int bRow = (lane & 7) + ((lane >> 4) << 3);
    const int bCol = ((lane >> 3) & 1) * 4;

    float acc[2][8][4];
#pragma unroll
    for (int mt = 0; mt < 2; mt++)
#pragma unroll
        for (int nt = 0; nt < 8; nt++)
#pragma unroll
            for (int i = 0; i < 4; i++) acc[mt][nt][i] = 0.f;

    const int KT = (KP + 15) >> 4;

    auto fill = [&](int kt, int s) {
        int kp0 = kt * 16;
        uint32_t stage = smem_u32 + s * STAGE_BYTES;
#pragma unroll
        for (int t = 0; t < 2; t++) {
            int ci  = tid + t * 256;
            int m   = ci >> 2;
            int cp4 = (ci & 3) * 4;
            uint32_t doff = (uint32_t)(m * 20 + cp4) * 4u;
            int gm = row0 + m;
            long aoff = (long)gm * LDP + kp0 + cp4;
            int szA = (gm < M) ? 16 : 0;
            cp_async16(stage + doff,                 Apk_h + aoff, szA);
            cp_async16(stage + ARR_BYTES + doff,     Apk_l + aoff, szA);
            int gn = col0 + m;
            long boff = (long)gn * LDP + kp0 + cp4;
            int szB = (gn < N) ? 16 : 0;
            cp_async16(stage + 2 * ARR_BYTES + doff, Bpk_h + boff, szB);
            cp_async16(stage + 3 * ARR_BYTES + doff, Bpk_l + boff, szB);
        }
    };

    fill(0, 0);
    asm volatile("cp.async.commit_group;");

    for (int kt = 0; kt < KT; kt++) {
        int s = kt & 1;
        if (kt + 1 < KT) {
            fill(kt + 1, (kt + 1) & 1);
            asm volatile("cp.async.commit_group;");
            asm volatile("cp.async.wait_group 1;");
        } else {
            asm volatile("cp.async.wait_group 0;");
        }
        __syncthreads();

        uint32_t baseAh = smem_u32 + s * STAGE_BYTES;
        uint32_t baseAl = baseAh + ARR_BYTES;
        uint32_t baseBh = baseAh + 2 * ARR_BYTES;
        uint32_t baseBl = baseAh + 3 * ARR_BYTES;

#pragma unroll
        for (int ks = 0; ks < 2; ks++) {
            uint32_t ah[2][4], al[2][4];
#pragma unroll
            for (int mt = 0; mt < 2; mt++) {
                uint32_t off = (uint32_t)((wm * 32 + mt * 16 + aRow) * 20 + ks * 8 + aCol) * 4u;
                ldsm_x4(ah[mt][0], ah[mt][1], ah[mt][2], ah[mt][3], baseAh + off);
                ldsm_x4(al[mt][0], al[mt][1], al[mt][2], al[mt][3], baseAl + off);
            }
#pragma unroll
            for (int ntp = 0; ntp < 4; ntp++) {
                uint32_t off = (uint32_t)((wn * 64 + ntp * 16 + bRow) * 20 + ks * 8 + bCol) * 4u;
                uint32_t bh[4], bl[4];
                ldsm_x4(bh[0], bh[1], bh[2], bh[3], baseBh + off);
                ldsm_x4(bl[0], bl[1], bl[2], bl[3], baseBl + off);
#pragma unroll
                for (int sub = 0; sub < 2; sub++) {
                    int nt = ntp * 2 + sub;
#pragma unroll
                    for (int mt = 0; mt < 2; mt++) {
                        mma16816(acc[mt][nt], ah[mt], bh[sub * 2], bh[sub * 2 + 1]);
                        mma16816(acc[mt][nt], al[mt], bh[sub * 2], bh[sub * 2 + 1]);
                        mma16816(acc[mt][nt], ah[mt], bl[sub * 2], bl[sub * 2 + 1]);
                    }
                }
            }
        }
        __syncthreads();
    }

#pragma unroll
    for (int mt = 0; mt < 2; mt++) {
        int rm0 = row0 + wm * 32 + mt * 16 + r;
        int rm1 = rm0 + 8;
#pragma unroll
        for (int nt = 0; nt < 8; nt++) {
            int cn = col0 + wn * 64 + nt * 8 + q4 * 2;
#pragma unroll
            for (int jj = 0; jj < 2; jj++) {
                int gn = cn + jj;
                if (gn >= N) continue;
                bool phi = phiH && (gn % DD) >= SD;
                if (rm0 < M) {
                    float v = acc[mt][nt][jj];
                    if (phi) v = (v > 0.f) ? v + 1.f : __expf(v);
                    C[rm0 * ldc + gn] = v;
                }
                if (rm1 < M) {
                    float v = acc[mt][nt][2 + jj];
                    if (phi) v = (v > 0.f) ? v + 1.f : __expf(v);
                    C[rm1 * ldc + gn] = v;
                }
            }
        }
    }
}

// ---------------------------------------------------------------------------
// Fused attn+Wh GEMM: b[n,o] = sum_{h,m} (phiQh[n,h,m]*invDH[n,h]) * Mb[o][h*240+m]
// A: Yq h-part, strided + scaled + cvt in-loop. B: packed Mb (u32 loads).
// K = 1920 (60 k-tiles), N = 240.
// ---------------------------------------------------------------------------
__global__ __launch_bounds__(256, 2) void fused_bh_gemm(
    const float* __restrict__ Yq,
    const float* __restrict__ invDH,
    const uint32_t* __restrict__ Bpk_h, const uint32_t* __restrict__ Bpk_l,
    float* __restrict__ bb)
{
    __shared__ uint32_t Ah[128][20], Al[128][20], Bh[128][20], Bl[128][20];

    const int tid  = threadIdx.x;
    const int lane = tid & 31;
    const int wid  = tid >> 5;
    const int wm   = wid & 3;
    const int wn   = wid >> 2;
    const int row0 = blockIdx.y * 128;
    const int col0 = blockIdx.x * 128;
    const int r    = lane >> 2;
    const int q4   = lane & 3;

    const int aRow = (lane & 15);
    const int aCol = (lane >> 4) * 4;
    const int bRow = (lane & 7) + ((lane >> 4) << 3);
    const int bCol = ((lane >> 3) & 1) * 4;

    float acc[2][8][4];
#pragma unroll
    for (int mt = 0; mt < 2; mt++)
#pragma unroll
        for (int nt = 0; nt < 8; nt++)
#pragma unroll
            for (int i = 0; i < 4; i++) acc[mt][nt][i] = 0.f;

    for (int kt = 0; kt < 60; kt++) {
        int k0 = kt * 32;
        // A fill: strided gather + per-(n,h) scale + cvt
#pragma unroll
        for (int i = 0; i < 8; i++) {
            int idx = tid + i * 256;
            int m = idx >> 4, kp = idx & 15;
            int gm = row0 + m;
            int gk = k0 + kp * 2;          // even; pair never straddles heads (240 even)
            int h  = gk / OSD;
            int col = gk - h * OSD;
            float x0 = 0.f, x1 = 0.f;
            if (gm < NROWS) {
                float sc = invDH[gm * HH + h];
                const float* p = Yq + (long)gm * FF + h * DD + SD + col;
                x0 = p[0] * sc;
                x1 = p[1] * sc;
            }
            uint32_t hp, lp; cvt_pack(x0, x1, hp, lp);
            Ah[m][kp] = hp; Al[m][kp] = lp;
        }
        // B fill: packed u32 loads
#pragma unroll
        for (int i = 0; i < 8; i++) {
            int idx = tid + i * 256;
            int n = idx >> 4, kp = idx & 15;
            int gn = col0 + n;
            int gkp = kt * 16 + kp;
            bool ok = (gn < OSD);
            Bh[n][kp] = ok ? __ldg(&Bpk_h[gn * CHP + gkp]) : 0u;
            Bl[n][kp] = ok ? __ldg(&Bpk_l[gn * CHP + gkp]) : 0u;
        }
        __syncthreads();

#pragma unroll
        for (int ks = 0; ks < 2; ks++) {
            uint32_t ah[2][4], al[2][4];
#pragma unroll
            for (int mt = 0; mt < 2; mt++) {
                int m_ = wm * 32 + mt * 16 + aRow;
                int c_ = ks * 8 + aCol;
                ldsm_x4(ah[mt][0], ah[mt][1], ah[mt][2], ah[mt][3], smem_addr(&Ah[m_][c_]));
                ldsm_x4(al[mt][0], al[mt][1], al[mt][2], al[mt][3], smem_addr(&Al[m_][c_]));
            }
#pragma unroll
            for (int ntp = 0; ntp < 4; ntp++) {
                int n_ = wn * 64 + ntp * 16 + bRow;
                int c_ = ks * 8 + bCol;
                uint32_t bh[4], bl[4];
                ldsm_x4(bh[0], bh[1], bh[2], bh[3], smem_addr(&Bh[n_][c_]));
                ldsm_x4(bl[0], bl[1], bl[2], bl[3], smem_addr(&Bl[n_][c_]));
#pragma unroll
                for (int sub = 0; sub < 2; sub++) {
                    int nt = ntp * 2 + sub;
#pragma unroll
                    for (int mt = 0; mt < 2; mt++) {
                        mma16816(acc[mt][nt], ah[mt], bh[sub * 2], bh[sub * 2 + 1]);
                        mma16816(acc[mt][nt], al[mt], bh[sub * 2], bh[sub * 2 + 1]);
                        mma16816(acc[mt][nt], ah[mt], bl[sub * 2], bl[sub * 2 + 1]);
                    }
                }
            }
        }
        __syncthreads();
    }

#pragma unroll
    for (int mt = 0; mt < 2; mt++) {
        int rm0 = row0 + wm * 32 + mt * 16 + r;
        int rm1 = rm0 + 8;
#pragma unroll
        for (int nt = 0; nt < 8; nt++) {
            int cn = col0 + wn * 64 + nt * 8 + q4 * 2;
#pragma unroll
            for (int jj = 0; jj < 2; jj++) {
                int gn = cn + jj;
                if (gn >= OSD) continue;
                if (rm0 < NROWS) bb[rm0 * OSD + gn] = acc[mt][nt][jj];
                if (rm1 < NROWS) bb[rm1 * OSD + gn] = acc[mt][nt][2 + jj];
            }
        }
    }
}

// ---------------------------------------------------------------------------
// ktv h-block (TN): ktvT[h][d+SD][m+SD] = sum_n phiKh[n,m] * Vh[n,d]
// ---------------------------------------------------------------------------
#define KTV_NSPLIT 20
__global__ __launch_bounds__(256, 2) void ktv_bf16s_tn(
    const float* __restrict__ Yk, const float* __restrict__ Yv,
    float* __restrict__ ktvT)
{
    __shared__ uint32_t Ah[128][20], Al[128][20], Bh[128][20], Bl[128][20];

    const int h  = blockIdx.z / KTV_NSPLIT;
    const int sp = blockIdx.z % KTV_NSPLIT;
    const int m0 = blockIdx.x * 128;
    const int d0 = blockIdx.y * 128;
    const int chunk = (NROWS + KTV_NSPLIT - 1) / KTV_NSPLIT;
    const int n0 = sp * chunk;
    int n1 = n0 + chunk; if (n1 > NROWS) n1 = NROWS;

    const float* Kp = Yk + h * DD + SD;
    const float* Vp = Yv + h * DD + SD;

    const int tid  = threadIdx.x;
    const int lane = tid & 31;
    const int wid  = tid >> 5;
    const int wm   = wid & 3;
    const int wn   = wid >> 2;
    const int r    = lane >> 2;
    const int q4   = lane & 3;

    const int aRow = (lane & 15);
    const int aCol = (lane >> 4) * 4;
    const int bRow = (lane & 7) + ((lane >> 4) << 3);
    const int bCol = ((lane >> 3) & 1) * 4;

    float acc[2][8][4];
#pragma unroll
    for (int mt = 0; mt < 2; mt++)
#pragma unroll
        for (int nt = 0; nt < 8; nt++)
#pragma unroll
            for (int i = 0; i < 4; i++) acc[mt][nt][i] = 0.f;

    for (int kb = n0; kb < n1; kb += 32) {
#pragma unroll
        for (int i = 0; i < 8; i++) {
            int idx = tid + i * 256;
            int m = idx & 127, np = idx >> 7;
            int gm = m0 + m;
            int gn = kb + np * 2;
            bool mok = (gm < OSD);
            float x0 = (mok && gn     < n1) ? __ldg(&Kp[gn * FF + gm])       : 0.f;
            float x1 = (mok && gn + 1 < n1) ? __ldg(&Kp[(gn + 1) * FF + gm]) : 0.f;
            uint32_t hp, lp; cvt_pack(x0, x1, hp, lp);
            Ah[m][np] = hp; Al[m][np] = lp;
        }
#pragma unroll
        for (int i = 0; i < 8; i++) {
            int idx = tid + i * 256;
            int d = idx & 127, np = idx >> 7;
            int gd = d0 + d;
            int gn = kb + np * 2;
            bool dok = (gd < OSD);
            float x0 = (dok && gn     < n1) ? __ldg(&Vp[gn * FF + gd])       : 0.f;
            float x1 = (dok && gn + 1 < n1) ? __ldg(&Vp[(gn + 1) * FF + gd]) : 0.f;
            uint32_t hp, lp; cvt_pack(x0, x1, hp, lp);
            Bh[d][np] = hp; Bl[d][np] = lp;
        }
        __syncthreads();

#pragma unroll
        for (int ks = 0; ks < 2; ks++) {
            uint32_t ah[2][4], al[2][4];
#pragma unroll
            for (int mt = 0; mt < 2; mt++) {
                int m_ = wm * 32 + mt * 16 + aRow;
                int c_ = ks * 8 + aCol;
                ldsm_x4(ah[mt][0], ah[mt][1], ah[mt][2], ah[mt][3], smem_addr(&Ah[m_][c_]));
                ldsm_x4(al[mt][0], al[mt][1], al[mt][2], al[mt][3], smem_addr(&Al[m_][c_]));
            }
#pragma unroll
            for (int ntp = 0; ntp < 4; ntp++) {
                int n_ = wn * 64 + ntp * 16 + bRow;
                int c_ = ks * 8 + bCol;
                uint32_t bh[4], bl[4];
                ldsm_x4(bh[0], bh[1], bh[2], bh[3], smem_addr(&Bh[n_][c_]));
                ldsm_x4(bl[0], bl[1], bl[2], bl[3], smem_addr(&Bl[n_][c_]));
#pragma unroll
                for (int sub = 0; sub < 2; sub++) {
                    int nt = ntp * 2 + sub;
#pragma unroll
                    for (int mt = 0; mt < 2; mt++) {
                        mma16816(acc[mt][nt], ah[mt], bh[sub * 2], bh[sub * 2 + 1]);
                        mma16816(acc[mt][nt], al[mt], bh[sub * 2], bh[sub * 2 + 1]);
                        mma16816(acc[mt][nt], ah[mt], bl[sub * 2], bl[sub * 2 + 1]);
                    }
                }
            }
        }
        __syncthreads();
    }

    float* kt = ktvT + h * DD * DD;
#pragma unroll
    for (int mt = 0; mt < 2; mt++) {
        int gm0 = m0 + wm * 32 + mt * 16 + r;
        int gm1 = gm0 + 8;
#pragma unroll
        for (int nt = 0; nt < 8; nt++) {
            int gd = d0 + wn * 64 + nt * 8 + q4 * 2;
#pragma unroll
            for (int jj = 0; jj < 2; jj++) {
                int d = gd + jj;
                if (d >= OSD) continue;
                if (gm0 < OSD) atomicAdd(&kt[(d + SD) * DD + (gm0 + SD)], acc[mt][nt][jj]);
                if (gm1 < OSD) atomicAdd(&kt[(d + SD) * DD + (gm1 + SD)], acc[mt][nt][2 + jj]);
            }
        }
    }
}

// --------- s-block ktv ------------------------------------------------------
#define KTVS_NCHUNK 100
__global__ __launch_bounds__(320) void ktvs_kernel(
    const float* __restrict__ Yk, const float* __restrict__ Yv,
    float* __restrict__ ktvs)
{
    __shared__ float sk[SD], sv[SD];
    int h  = blockIdx.y;
    int cn = blockIdx.x;
    int chunk = (NROWS + KTVS_NCHUNK - 1) / KTVS_NCHUNK;
    int n0 = cn * chunk;
    int n1 = n0 + chunk; if (n1 > NROWS) n1 = NROWS;
    int t = threadIdx.x;
    int m = t / SD, d = t - m * SD;
    bool act = (t < SD * SD);
    float acc = 0.f;
    for (int n = n0; n < n1; n++) {
        if (t < SD)            sk[t]      = Yk[n * FF + h * DD + t];
        else if (t < 2 * SD)   sv[t - SD] = Yv[n * FF + h * DD + (t - SD)];
        __syncthreads();
        if (act) acc += sk[m] * sv[d];
        __syncthreads();
    }
    if (act) atomicAdd(&ktvs[h * SD * SD + m * SD + d], acc);
}

// --------- s-part attention fused: cs = (phiQs @ ktvs) / denS --------------
__global__ void cs_kernel(const float* __restrict__ Yq,
                          const float* __restrict__ ktvs,
                          const float* __restrict__ dS,
                          float* __restrict__ cs)
{
    int warp = (blockIdx.x * blockDim.x + threadIdx.x) >> 5;
    int lane = threadIdx.x & 31;
    if (warp >= NROWS * HH) return;
    int n = warp / HH, h = warp - n * HH;
    const float* q = Yq + n * FF + h * DD;
    const float* kt = ktvs + h * SD * SD;
    float qv = (lane < SD) ? q[lane] : 0.f;
    float acc = 0.f;
#pragma unroll
    for (int m = 0; m < SD; m++) {
        float qm = __shfl_sync(0xffffffffu, qv, m);
        if (lane < SD) acc += qm * kt[m * SD + lane];
    }
    if (lane < SD) cs[n * (HH * SD) + h * SD + lane] = acc / (dS[n * HH + h] + 1e-6f);
}

// --------- s-part pseudo-linear fixup --------------------------------------
__global__ void ep1s_kernel(float* __restrict__ Y, int do_phi)
{
    int warp = (blockIdx.x * blockDim.x + threadIdx.x) >> 5;
    int lane = threadIdx.x & 31;
    if (warp >= NROWS * HH) return;
    int n = warp / HH, h = warp - n * HH;
    float* p = Y + n * FF + h * DD;
    float x = (lane < SD) ? p[lane] : 0.f;
    float ss = x * x;
#pragma unroll
    for (int o = 16; o > 0; o >>= 1) ss += __shfl_xor_sync(0xffffffffu, ss, o);
    float scale = 1.f / (sqrtf(ss) + 1e-8f);
    if (lane < SD) {
        float y = x * scale;
        if (do_phi) y = (y > 0.f) ? y + 1.f : __expf(y);
        p[lane] = y;
    }
}

__global__ void zero_kernel(float* __restrict__ p, int n)
{
    int i = blockIdx.x * blockDim.x + threadIdx.x;
    if (i < n) p[i] = 0.f;
}

// --------- column sums of phiK ---------------------------------------------
__global__ void colsum_kernel(const float* __restrict__ Y, float* __restrict__ out)
{
    int f = blockIdx.x * blockDim.x + threadIdx.x;
    if (f >= FF) return;
    int n0 = blockIdx.y * 750;
    int n1 = n0 + 750; if (n1 > NROWS) n1 = NROWS;
    float s = 0.f;
    for (int n = n0; n < n1; n++) s += Y[n * FF + f];
    atomicAdd(&out[f], s);
}

// --------- den_s / inv den_h per (n,h) -------------------------------------
__global__ void den_kernel(const float* __restrict__ PQ,
                           const float* __restrict__ sumK,
                           float* __restrict__ dS, float* __restrict__ invDH)
{
    int n = blockIdx.x;
    int h = threadIdx.x >> 5;
    int lane = threadIdx.x & 31;
    const float* p = PQ + n * FF + h * DD;
    const float* s = sumK + h * DD;
    float as = 0.f, ah = 0.f;
    for (int m = lane; m < DD; m += 32) {
        float v = p[m] * s[m];
        if (m < SD) as += v; else ah += v;
    }
#pragma unroll
    for (int o = 16; o > 0; o >>= 1) {
        as += __shfl_xor_sync(0xffffffffu, as, o);
        ah += __shfl_xor_sync(0xffffffffu, ah, o);
    }
    if (lane == 0) {
        dS[n * HH + h] = as;
        invDH[n * HH + h] = 1.f / (ah + 1e-8f);
    }
}

// --------- a = c_s @ Ws^T, att_s = a / max(||a||,1e-12) --------------------
__global__ void a_kernel(const float* __restrict__ cs,
                         const float* __restrict__ Ws,
                         float* __restrict__ atts)
{
    __shared__ float ws[SD * 136];
    for (int i = threadIdx.x; i < SD * 136; i += blockDim.x) ws[i] = Ws[i];
    __syncthreads();
    int warp = threadIdx.x >> 5, lane = threadIdx.x & 31;
    int n = blockIdx.x * 8 + warp;
    if (n >= NROWS) return;
    float acc[SD];
#pragma unroll
    for (int o = 0; o < SD; o++) acc[o] = 0.f;
    for (int f = lane; f < 136; f += 32) {
        float x = cs[n * 136 + f];
#pragma unroll
        for (int o = 0; o < SD; o++) acc[o] += x * ws[o * 136 + f];
    }
#pragma unroll
    for (int o = 0; o < SD; o++)
#pragma unroll
        for (int s = 16; s > 0; s >>= 1)
            acc[o] += __shfl_xor_sync(0xffffffffu, acc[o], s);
    if (lane == 0) {
        float ss = 0.f;
#pragma unroll
        for (int o = 0; o < SD; o++) ss += acc[o] * acc[o];
        float sc = 1.f / fmaxf(sqrtf(ss), 1e-12f);
#pragma unroll
        for (int o = 0; o < SD; o++) atts[n * SD + o] = acc[o] * sc;
    }
}

// --------- final epilogue ---------------------------------------------------
__global__ void final_kernel(const float* __restrict__ b,
                             const float* __restrict__ atts,
                             float* __restrict__ out)
{
    int warp = threadIdx.x >> 5, lane = threadIdx.x & 31;
    int n = blockIdx.x * 8 + warp;
    if (n >= NROWS) return;
    const float* br = b + n * OSD;
    float ss = 0.f;
    for (int j = lane; j < OSD; j += 32) { float v = br[j]; ss += v * v; }
#pragma unroll
    for (int s = 16; s > 0; s >>= 1) ss += __shfl_xor_sync(0xffffffffu, ss, s);
    float nr  = sqrtf(ss);
    float bn  = nr + 1e-8f;
    float bnc = fminf(bn, 1e6f);
    float bt  = sqrtf(bnc * bnc + 1.0f);
    float scale = (bn > 1e6f) ? (1e6f / fmaxf(nr, 1e-12f * bnc)) : 1.0f;
    float* o = out + n * DD;
    for (int j = lane; j < OSD; j += 32) o[SD + j] = br[j] * scale;
    if (lane < SD) o[lane] = bt * atts[n * SD + lane];
}

// ---------------------------------------------------------------------------
extern "C" void kernel_launch(void* const* d_in, const int* in_sizes, int n_in,
                              void* d_out, int out_size)
{
    const float* qin = (const float*)d_in[0];
    const float* sin = (const float*)d_in[1];
    const float* Wq  = (const float*)d_in[2];
    const float* Wk  = (const float*)d_in[3];
    const float* Wv  = (const float*)d_in[4];
    const float* Ws  = (const float*)d_in[5];
    const float* Wh  = (const float*)d_in[6];
    float* out = (float*)d_out;

    float *Yq, *Yk, *Yv, *ktvT, *ktvs, *sumK, *dS, *invDH, *cs, *atts, *bb, *Mb;
    uint32_t *Xqh, *Xql, *Xsh, *Xsl, *Wqh, *Wql, *Wkh, *Wkl, *Wvh, *Wvl, *Mbh, *Mbl;
    cudaGetSymbolAddress((void**)&Yq,   g_Yq);
    cudaGetSymbolAddress((void**)&Yk,   g_Yk);
    cudaGetSymbolAddress((void**)&Yv,   g_Yv);
    cudaGetSymbolAddress((void**)&ktvT, g_ktvT);
    cudaGetSymbolAddress((void**)&ktvs, g_ktvs);
    cudaGetSymbolAddress((void**)&sumK, g_sumK);
    cudaGetSymbolAddress((void**)&dS,   g_denS);
    cudaGetSymbolAddress((void**)&invDH, g_invDH);
    cudaGetSymbolAddress((void**)&cs,   g_cs);
    cudaGetSymbolAddress((void**)&atts, g_atts);
    cudaGetSymbolAddress((void**)&bb,   g_b);
    cudaGetSymbolAddress((void**)&Mb,   g_Mb);
    cudaGetSymbolAddress((void**)&Xqh,  g_Xq_hi); cudaGetSymbolAddress((void**)&Xql, g_Xq_lo);
    cudaGetSymbolAddress((void**)&Xsh,  g_Xs_hi); cudaGetSymbolAddress((void**)&Xsl, g_Xs_lo);
    cudaGetSymbolAddress((void**)&Wqh,  g_Wq_hi); cudaGetSymbolAddress((void**)&Wql, g_Wq_lo);
    cudaGetSymbolAddress((void**)&Wkh,  g_Wk_hi); cudaGetSymbolAddress((void**)&Wkl, g_Wk_lo);
    cudaGetSymbolAddress((void**)&Wvh,  g_Wv_hi); cudaGetSymbolAddress((void**)&Wvl, g_Wv_lo);
    cudaGetSymbolAddress((void**)&Mbh,  g_Mb_hi); cudaGetSymbolAddress((void**)&Mbl, g_Mb_lo);

    // one-time setup (runs on the uncaptured correctness call first)
    static int inited = 0;
    static cudaStream_t sB;
    static cudaEvent_t eFork, eZero, eProjK, eProjV, eDen, eA;
    if (!inited) {
        cudaFuncSetAttribute(gemm_pp_db, cudaFuncAttributeMaxDynamicSharedMemorySize, 2 * STAGE_BYTES);
        cudaStreamCreateWithFlags(&sB, cudaStreamNonBlocking);
        cudaEventCreateWithFlags(&eFork,  cudaEventDisableTiming);
        cudaEventCreateWithFlags(&eZero,  cudaEventDisableTiming);
        cudaEventCreateWithFlags(&eProjK, cudaEventDisableTiming);
        cudaEventCreateWithFlags(&eProjV, cudaEventDisableTiming);
        cudaEventCreateWithFlags(&eDen,   cudaEventDisableTiming);
        cudaEventCreateWithFlags(&eA,     cudaEventDisableTiming);
        inited = 1;
    }

    const int rowTiles = (NROWS + 127) / 128;   // 235
    const int fTiles   = (FF + 127) / 128;      // 17
    const int KPX      = 129;                   // pairs for K=257

    // ---- fork stream B off stream 0 ----
    cudaEventRecord(eFork, 0);
    cudaStreamWaitEvent(sB, eFork, 0);

    // stream 0: packs needed by projK / projV
    pack_kernel<<<(NROWS * LDP + 255) / 256, 256, 0, 0>>>(sin, Xsh, Xsl, NROWS, DD, DD, LDP);
    pack_kernel<<<(FF * LDP + 255) / 256, 256, 0, 0>>>(Wk, Wkh, Wkl, FF, DD, DD, LDP);
    pack_kernel<<<(FF * LDP + 255) / 256, 256, 0, 0>>>(Wv, Wvh, Wvl, FF, DD, DD, LDP);

    // stream B: packs for projQ + zero accumulators
    pack_kernel<<<(NROWS * LDP + 255) / 256, 256, 0, sB>>>(qin, Xqh, Xql, NROWS, DD, DD, LDP);
    pack_kernel<<<(FF * LDP + 255) / 256, 256, 0, sB>>>(Wq, Wqh, Wql, FF, DD, DD, LDP);
    zero_kernel<<<(HH * DD * DD + 255) / 256, 256, 0, sB>>>(ktvT, HH * DD * DD);
    zero_kernel<<<(HH * SD * SD + 255) / 256, 256, 0, sB>>>(ktvs, HH * SD * SD);
    zero_kernel<<<(FF + 255) / 256, 256, 0, sB>>>(sumK, FF);
    cudaEventRecord(eZero, sB);

    // stream 0: projK, projV (backbone)
    gemm_pp_db<<<dim3(fTiles, rowTiles), 256, 2 * STAGE_BYTES, 0>>>(
        Xsh, Xsl, Wkh, Wkl, Yk, NROWS, FF, KPX, FF, 1);
    cudaEventRecord(eProjK, 0);
    gemm_pp_db<<<dim3(fTiles, rowTiles), 256, 2 * STAGE_BYTES, 0>>>(
        Xsh, Xsl, Wvh, Wvl, Yv, NROWS, FF, KPX, FF, 0);
    cudaEventRecord(eProjV, 0);

    // stream B: projQ + its s-part fixup (concurrent with stream 0 GEMMs)
    gemm_pp_db<<<dim3(fTiles, rowTiles), 256, 2 * STAGE_BYTES, sB>>>(
        Xqh, Xql, Wqh, Wql, Yq, NROWS, FF, KPX, FF, 1);
    ep1s_kernel<<<NROWS, 256, 0, sB>>>(Yq, 1);

    // stream 0: ktv (reads h-part only; doesn't need ep1s) after zeros
    cudaStreamWaitEvent(0, eZero, 0);
    ktv_bf16s_tn<<<dim3(2, 2, HH * KTV_NSPLIT), 256, 0, 0>>>(Yk, Yv, ktvT);

    // stream 0: M_h = ktv_h @ Wh_h^T (fp32), then pack for the fused GEMM
    mh_kernel<<<dim3(15, 15, HH), 256, 0, 0>>>(ktvT, Wh, Mb);
    pack_kernel<<<(OSD * CHP + 255) / 256, 256, 0, 0>>>(Mb, Mbh, Mbl, OSD, HH * OSD, HH * OSD, CHP);

    // stream B: s-chain (overlaps ktv/mh on stream 0)
    cudaStreamWaitEvent(sB, eProjK, 0);
    ep1s_kernel<<<NROWS, 256, 0, sB>>>(Yk, 1);
    colsum_kernel<<<dim3((FF + 255) / 256, 40), 256, 0, sB>>>(Yk, sumK);
    cudaStreamWaitEvent(sB, eProjV, 0);
    ep1s_kernel<<<NROWS, 256, 0, sB>>>(Yv, 0);
    ktvs_kernel<<<dim3(KTVS_NCHUNK, HH), 320, 0, sB>>>(Yk, Yv, ktvs);
    den_kernel<<<NROWS, 256, 0, sB>>>(Yq, sumK, dS, invDH);
    cudaEventRecord(eDen, sB);
    cs_kernel<<<NROWS, 256, 0, sB>>>(Yq, ktvs, dS, cs);
    a_kernel<<<(NROWS + 7) / 8, 256, 0, sB>>>(cs, Ws, atts);
    cudaEventRecord(eA, sB);

    // stream 0: fused attn+Wh GEMM (needs Mb on 0 + invDH from B)
    cudaStreamWaitEvent(0, eDen, 0);
    fused_bh_gemm<<<dim3(2, rowTiles), 256, 0, 0>>>(Yq, invDH, Mbh, Mbl, bb);

    // stream 0: final epilogue (join stream B)
    cudaStreamWaitEvent(0, eA, 0);
    final_kernel<<<(NROWS + 7) / 8, 256, 0, 0>>>(bb, atts, out);
}

// round 15
// speedup vs baseline: 1.2982x; 1.0572x over previous
#include <cuda_runtime.h>
#include <cuda_bf16.h>
#include <stdint.h>
#include <math.h>

// Problem constants
#define NROWS 30000
#define HH    8
#define SD    17          // OT+1
#define OSD   240
#define DD    257         // IN_DIM == OUT_DIM
#define FF    2056        // H * 257
#define LDP   144         // padded pair-stride for packed X/W
#define CHP   960         // pair-stride for packed Mb (K=1920)
#define GJ    264         // padded j-stride of G (257 -> 264)

// ---------------- scratch (device globals; no runtime alloc allowed) -------
__device__ float    g_Yq[NROWS * FF];
__device__ float    g_Yk[NROWS * FF];
__device__ float    g_G[HH * OSD * GJ];    // G[h][m][j] = sum_n phiKh[n,m]*Xs[n,j]
__device__ float    g_P[HH * DD * OSD];    // P[h][j][o] = sum_d Wv_h[d,j]*Wh_h[o,d]
__device__ float    g_Vs[NROWS * 136];     // s-part of V (normalized in place)
__device__ float    g_ktvs[HH * SD * SD];
__device__ float    g_sumK[FF];
__device__ float    g_denS[NROWS * HH];
__device__ float    g_invDH[NROWS * HH];
__device__ float    g_cs[NROWS * HH * SD];
__device__ float    g_atts[NROWS * SD];
__device__ float    g_b[NROWS * OSD];
__device__ float    g_Mb[OSD * HH * OSD];  // Mb[o][h*240+m] = M_h[m,o]
__device__ uint32_t g_Xq_hi[NROWS * LDP], g_Xq_lo[NROWS * LDP];
__device__ uint32_t g_Xs_hi[NROWS * LDP], g_Xs_lo[NROWS * LDP];
__device__ uint32_t g_Wq_hi[FF * LDP],    g_Wq_lo[FF * LDP];
__device__ uint32_t g_Wk_hi[FF * LDP],    g_Wk_lo[FF * LDP];
__device__ uint32_t g_WvS_hi[136 * LDP],  g_WvS_lo[136 * LDP];
__device__ uint32_t g_Mb_hi[OSD * CHP],   g_Mb_lo[OSD * CHP];

// ---------------------------------------------------------------------------
__device__ __forceinline__ void mma16816(float c[4], const uint32_t a[4], const uint32_t b0, const uint32_t b1)
{
    asm volatile(
        "mma.sync.aligned.m16n8k16.row.col.f32.bf16.bf16.f32 "
        "{%0,%1,%2,%3}, {%4,%5,%6,%7}, {%8,%9}, {%0,%1,%2,%3};\n"
        : "+f"(c[0]), "+f"(c[1]), "+f"(c[2]), "+f"(c[3])
        : "r"(a[0]), "r"(a[1]), "r"(a[2]), "r"(a[3]), "r"(b0), "r"(b1));
}

__device__ __forceinline__ void ldsm_x4(uint32_t& r0, uint32_t& r1, uint32_t& r2, uint32_t& r3, uint32_t addr)
{
    asm volatile("ldmatrix.sync.aligned.m8n8.x4.shared.b16 {%0,%1,%2,%3}, [%4];"
                 : "=r"(r0), "=r"(r1), "=r"(r2), "=r"(r3) : "r"(addr));
}

__device__ __forceinline__ uint32_t smem_addr(const void* p)
{
    return (uint32_t)__cvta_generic_to_shared(p);
}

__device__ __forceinline__ void cp_async16(uint32_t dst, const void* src, int src_bytes)
{
    asm volatile("cp.async.cg.shared.global [%0], [%1], 16, %2;"
                 :: "r"(dst), "l"(src), "r"(src_bytes));
}

__device__ __forceinline__ void cvt_pack(float x0, float x1, uint32_t& hp, uint32_t& lp)
{
    __nv_bfloat16 h0 = __float2bfloat16(x0);
    __nv_bfloat16 h1 = __float2bfloat16(x1);
    __nv_bfloat16 l0 = __float2bfloat16(x0 - __bfloat162float(h0));
    __nv_bfloat16 l1 = __float2bfloat16(x1 - __bfloat162float(h1));
    __nv_bfloat162 hh; hh.x = h0; hh.y = h1;
    __nv_bfloat162 ll; ll.x = l0; ll.y = l1;
    hp = *reinterpret_cast<uint32_t*>(&hh);
    lp = *reinterpret_cast<uint32_t*>(&ll);
}

// --------- pack fp32 matrix into bf16x2 hi/lo pair arrays ------------------
__global__ void pack_kernel(const float* __restrict__ src,
                            uint32_t* __restrict__ hi, uint32_t* __restrict__ lo,
                            int rows, int K, int ld, int ldp)
{
    int idx = blockIdx.x * blockDim.x + threadIdx.x;
    if (idx >= rows * ldp) return;
    int r_ = idx / ldp, kp = idx - r_ * ldp;
    int k = kp * 2;
    float x0 = (k < K)     ? src[r_ * ld + k]     : 0.f;
    float x1 = (k + 1 < K) ? src[r_ * ld + k + 1] : 0.f;
    uint32_t hp, lp; cvt_pack(x0, x1, hp, lp);
    hi[idx] = hp; lo[idx] = lp;
}

// --------- pack Wv s-rows (row r -> Wv row (r/17)*257 + (r%17)) ------------
__global__ void pack_wvs_kernel(const float* __restrict__ Wv,
                                uint32_t* __restrict__ hi, uint32_t* __restrict__ lo)
{
    int idx = blockIdx.x * blockDim.x + threadIdx.x;
    if (idx >= 136 * LDP) return;
    int r_ = idx / LDP, kp = idx - r_ * LDP;
    int k = kp * 2;
    const float* src = Wv + (long)((r_ / SD) * DD + (r_ % SD)) * DD;
    float x0 = (k < DD)     ? src[k]     : 0.f;
    float x1 = (k + 1 < DD) ? src[k + 1] : 0.f;
    uint32_t hp, lp; cvt_pack(x0, x1, hp, lp);
    hi[idx] = hp; lo[idx] = lp;
}

// ---------------------------------------------------------------------------
// Packed double-buffered GEMM (cp.async): C[m,n] = sum_k A[m,k]*B[n,k].
// ---------------------------------------------------------------------------
#define STAGE_BYTES 40960
#define ARR_BYTES   10240
__global__ __launch_bounds__(256, 2) void gemm_pp_db(
    const uint32_t* __restrict__ Apk_h, const uint32_t* __restrict__ Apk_l,
    const uint32_t* __restrict__ Bpk_h, const uint32_t* __restrict__ Bpk_l,
    float* __restrict__ C,
    int M, int N, int KP, int ldc, int phiH)
{
    extern __shared__ char smem[];
    const uint32_t smem_u32 = smem_addr(smem);

    const int tid  = threadIdx.x;
    const int lane = tid & 31;
    const int wid  = tid >> 5;
    const int wm   = wid & 3;
    const int wn   = wid >> 2;
    const int row0 = blockIdx.y * 128;
    const int col0 = blockIdx.x * 128;
    const int r    = lane >> 2;
    const int q4   = lane & 3;

    const int aRow = (lane & 15);
    const int aCol = (lane >> 4) * 4;
    const int bRow = (lane & 7) + ((lane >> 4) << 3);
    const int bCol = ((lane >> 3) & 1) * 4;

    float acc[2][8][4];
#pragma unroll
    for (int mt = 0; mt < 2; mt++)
#pragma unroll
        for (int nt = 0; nt < 8; nt++)
#pragma unroll
            for (int i = 0; i < 4; i++) acc[mt][nt][i] = 0.f;

    const int KT = (KP + 15) >> 4;

    auto fill = [&](int kt, int s) {
        int kp0 = kt * 16;
        uint32_t stage = smem_u32 + s * STAGE_BYTES;
#pragma unroll
        for (int t = 0; t < 2; t++) {
            int ci  = tid + t * 256;
            int m   = ci >> 2;
            int cp4 = (ci & 3) * 4;
            uint32_t doff = (uint32_t)(m * 20 + cp4) * 4u;
            int gm = row0 + m;
            long aoff = (long)gm * LDP + kp0 + cp4;
            int szA = (gm < M) ? 16 : 0;
            cp_async16(stage + doff,                 Apk_h + aoff, szA);
            cp_async16(stage + ARR_BYTES + doff,     Apk_l + aoff, szA);
            int gn = col0 + m;
            long boff = (long)gn * LDP + kp0 + cp4;
            int szB = (gn < N) ? 16 : 0;
            cp_async16(stage + 2 * ARR_BYTES + doff, Bpk_h + boff, szB);
            cp_async16(stage + 3 * ARR_BYTES + doff, Bpk_l + boff, szB);
        }
    };

    fill(0, 0);
    asm volatile("cp.async.commit_group;");

    for (int kt = 0; kt < KT; kt++) {
        int s = kt & 1;
        if (kt + 1 < KT) {
            fill(kt + 1, (kt + 1) & 1);
            asm volatile("cp.async.commit_group;");
            asm volatile("cp.async.wait_group 1;");
        } else {
            asm volatile("cp.async.wait_group 0;");
        }
        __syncthreads();

        uint32_t baseAh = smem_u32 + s * STAGE_BYTES;
        uint32_t baseAl = baseAh + ARR_BYTES;
        uint32_t baseBh = baseAh + 2 * ARR_BYTES;
        uint32_t baseBl = baseAh + 3 * ARR_BYTES;

#pragma unroll
        for (int ks = 0; ks < 2; ks++) {
            uint32_t ah[2][4], al[2][4];
#pragma unroll
            for (int mt = 0; mt < 2; mt++) {
                uint32_t off = (uint32_t)((wm * 32 + mt * 16 + aRow) * 20 + ks * 8 + aCol) * 4u;
                ldsm_x4(ah[mt][0], ah[mt][1], ah[mt][2], ah[mt][3], baseAh + off);
                ldsm_x4(al[mt][0], al[mt][1], al[mt][2], al[mt][3], baseAl + off);
            }
#pragma unroll
            for (int ntp = 0; ntp < 4; ntp++) {
                uint32_t off = (uint32_t)((wn * 64 + ntp * 16 + bRow) * 20 + ks * 8 + bCol) * 4u;
                uint32_t bh[4], bl[4];
                ldsm_x4(bh[0], bh[1], bh[2], bh[3], baseBh + off);
                ldsm_x4(bl[0], bl[1], bl[2], bl[3], baseBl + off);
#pragma unroll
                for (int sub = 0; sub < 2; sub++) {
                    int nt = ntp * 2 + sub;
#pragma unroll
                    for (int mt = 0; mt < 2; mt++) {
                        mma16816(acc[mt][nt], ah[mt], bh[sub * 2], bh[sub * 2 + 1]);
                        mma16816(acc[mt][nt], al[mt], bh[sub * 2], bh[sub * 2 + 1]);
                        mma16816(acc[mt][nt], ah[mt], bl[sub * 2], bl[sub * 2 + 1]);
                    }
                }
            }
        }
        __syncthreads();
    }

#pragma unroll
    for (int mt = 0; mt < 2; mt++) {
        int rm0 = row0 + wm * 32 + mt * 16 + r;
        int rm1 = rm0 + 8;
#pragma unroll
        for (int nt = 0; nt < 8; nt++) {
            int cn = col0 + wn * 64 + nt * 8 + q4 * 2;
#pragma unroll
            for (int jj = 0; jj < 2; jj++) {
                int gn = cn + jj;
                if (gn >= N) continue;
                bool phi = phiH && (gn % DD) >= SD;
                if (rm0 < M) {
                    float v = acc[mt][nt][jj];
                    if (phi) v = (v > 0.f) ? v + 1.f : __expf(v);
                    C[(long)rm0 * ldc + gn] = v;
                }
                if (rm1 < M) {
                    float v = acc[mt][nt][2 + jj];
                    if (phi) v = (v > 0.f) ? v + 1.f : __expf(v);
                    C[(long)rm1 * ldc + gn] = v;
                }
            }
        }
    }
}

// ---------------------------------------------------------------------------
// G GEMM (TN over tokens): G[h][m][j] += sum_n phiKh[n,m] * Xs[n,j]
// m in [0,240), j in [0,256); split-K over n with atomics. Column j=256 is
// accumulated by colsum2.
// ---------------------------------------------------------------------------
#define KTV_NSPLIT 20
__global__ __launch_bounds__(256, 2) void g_gemm(
    const float* __restrict__ Yk, const float* __restrict__ Xs,
    float* __restrict__ G)
{
    __shared__ uint32_t Ah[128][20], Al[128][20], Bh[128][20], Bl[128][20];

    const int h  = blockIdx.z / KTV_NSPLIT;
    const int sp = blockIdx.z % KTV_NSPLIT;
    const int m0 = blockIdx.x * 128;
    const int j0 = blockIdx.y * 128;
    const int chunk = (NROWS + KTV_NSPLIT - 1) / KTV_NSPLIT;
    const int n0 = sp * chunk;
    int n1 = n0 + chunk; if (n1 > NROWS) n1 = NROWS;

    const float* Kp = Yk + h * DD + SD;

    const int tid  = threadIdx.x;
    const int lane = tid & 31;
    const int wid  = tid >> 5;
    const int wm   = wid & 3;
    const int wn   = wid >> 2;
    const int r    = lane >> 2;
    const int q4   = lane & 3;

    const int aRow = (lane & 15);
    const int aCol = (lane >> 4) * 4;
    const int bRow = (lane & 7) + ((lane >> 4) << 3);
    const int bCol = ((lane >> 3) & 1) * 4;

    float acc[2][8][4];
#pragma unroll
    for (int mt = 0; mt < 2; mt++)
#pragma unroll
        for (int nt = 0; nt < 8; nt++)
#pragma unroll
            for (int i = 0; i < 4; i++) acc[mt][nt][i] = 0.f;

    for (int kb = n0; kb < n1; kb += 32) {
#pragma unroll
        for (int i = 0; i < 8; i++) {
            int idx = tid + i * 256;
            int m = idx & 127, np = idx >> 7;
            int gm = m0 + m;
            int gn = kb + np * 2;
            bool mok = (gm < OSD);
            float x0 = (mok && gn     < n1) ? __ldg(&Kp[(long)gn * FF + gm])       : 0.f;
            float x1 = (mok && gn + 1 < n1) ? __ldg(&Kp[(long)(gn + 1) * FF + gm]) : 0.f;
            uint32_t hp, lp; cvt_pack(x0, x1, hp, lp);
            Ah[m][np] = hp; Al[m][np] = lp;
        }
#pragma unroll
        for (int i = 0; i < 8; i++) {
            int idx = tid + i * 256;
            int d = idx & 127, np = idx >> 7;
            int gj = j0 + d;
            int gn = kb + np * 2;
            bool jok = (gj < 256);
            float x0 = (jok && gn     < n1) ? __ldg(&Xs[(long)gn * DD + gj])       : 0.f;
            float x1 = (jok && gn + 1 < n1) ? __ldg(&Xs[(long)(gn + 1) * DD + gj]) : 0.f;
            uint32_t hp, lp; cvt_pack(x0, x1, hp, lp);
            Bh[d][np] = hp; Bl[d][np] = lp;
        }
        __syncthreads();

#pragma unroll
        for (int ks = 0; ks < 2; ks++) {
            uint32_t ah[2][4], al[2][4];
#pragma unroll
            for (int mt = 0; mt < 2; mt++) {
                int m_ = wm * 32 + mt * 16 + aRow;
                int c_ = ks * 8 + aCol;
                ldsm_x4(ah[mt][0], ah[mt][1], ah[mt][2], ah[mt][3], smem_addr(&Ah[m_][c_]));
                ldsm_x4(al[mt][0], al[mt][1], al[mt][2], al[mt][3], smem_addr(&Al[m_][c_]));
            }
#pragma unroll
            for (int ntp = 0; ntp < 4; ntp++) {
                int n_ = wn * 64 + ntp * 16 + bRow;
                int c_ = ks * 8 + bCol;
                uint32_t bh[4], bl[4];
                ldsm_x4(bh[0], bh[1], bh[2], bh[3], smem_addr(&Bh[n_][c_]));
                ldsm_x4(bl[0], bl[1], bl[2], bl[3], smem_addr(&Bl[n_][c_]));
#pragma unroll
                for (int sub = 0; sub < 2; sub++) {
                    int nt = ntp * 2 + sub;
#pragma unroll
                    for (int mt = 0; mt < 2; mt++) {
                        mma16816(acc[mt][nt], ah[mt], bh[sub * 2], bh[sub * 2 + 1]);
                        mma16816(acc[mt][nt], al[mt], bh[sub * 2], bh[sub * 2 + 1]);
                        mma16816(acc[mt][nt], ah[mt], bl[sub * 2], bl[sub * 2 + 1]);
                    }
                }
            }
        }
        __syncthreads();
    }

    float* Gp = G + (long)h * OSD * GJ;
#pragma unroll
    for (int mt = 0; mt < 2; mt++) {
        int gm0 = m0 + wm * 32 + mt * 16 + r;
        int gm1 = gm0 + 8;
#pragma unroll
        for (int nt = 0; nt < 8; nt++) {
            int gj = j0 + wn * 64 + nt * 8 + q4 * 2;
#pragma unroll
            for (int jj = 0; jj < 2; jj++) {
                int j = gj + jj;
                if (j >= 256) continue;
                if (gm0 < OSD) atomicAdd(&Gp[gm0 * GJ + j], acc[mt][nt][jj]);
                if (gm1 < OSD) atomicAdd(&Gp[gm1 * GJ + j], acc[mt][nt][2 + jj]);
            }
        }
    }
}

// ---------------------------------------------------------------------------
// P[h][j][o] = sum_d Wv[h][17+d][j] * Wh[o][h*240+d]  (weights only, fp32)
// ---------------------------------------------------------------------------
__global__ __launch_bounds__(256) void p_kernel(
    const float* __restrict__ Wv, const float* __restrict__ Wh,
    float* __restrict__ P)
{
    __shared__ float At[16][17], Bt[16][17];
    int h  = blockIdx.z;
    int j0 = blockIdx.x * 16;
    int o0 = blockIdx.y * 16;
    int tx = threadIdx.x & 15, ty = threadIdx.x >> 4;
    float acc = 0.f;
    for (int d0 = 0; d0 < OSD; d0 += 16) {
        int j = j0 + tx;
        At[ty][tx] = (j < DD) ? Wv[((long)h * DD + SD + d0 + ty) * DD + j] : 0.f;
        Bt[ty][tx] = Wh[(long)(o0 + tx) * (HH * OSD) + h * OSD + d0 + ty];
        __syncthreads();
#pragma unroll
        for (int dd = 0; dd < 16; dd++) acc += At[dd][tx] * Bt[dd][ty];
        __syncthreads();
    }
    int j = j0 + tx;
    if (j < DD) P[(long)h * DD * OSD + (long)j * OSD + (o0 + ty)] = acc;
}

// ---------------------------------------------------------------------------
// Mb[o][h*240+m] = M_h[m,o] = sum_j G[h][m][j] * P[h][j][o]   (fp32)
// ---------------------------------------------------------------------------
__global__ __launch_bounds__(256) void m_kernel(
    const float* __restrict__ G, const float* __restrict__ P,
    float* __restrict__ Mb)
{
    __shared__ float At[16][17], Bt[16][17];
    int h  = blockIdx.z;
    int m0 = blockIdx.x * 16;
    int o0 = blockIdx.y * 16;
    int tx = threadIdx.x & 15, ty = threadIdx.x >> 4;
    const float* Gp = G + (long)h * OSD * GJ;
    const float* Pp = P + (long)h * DD * OSD;
    float acc = 0.f;
    for (int j0 = 0; j0 < GJ; j0 += 16) {
        int j = j0 + ty;
        At[ty][tx] = (j < GJ) ? Gp[(m0 + tx) * GJ + j] : 0.f;
        Bt[ty][tx] = (j < DD) ? Pp[(long)j * OSD + (o0 + tx)] : 0.f;
        __syncthreads();
#pragma unroll
        for (int dd = 0; dd < 16; dd++) acc += At[dd][tx] * Bt[dd][ty];
        __syncthreads();
    }
    Mb[(long)(o0 + ty) * (HH * OSD) + h * OSD + (m0 + tx)] = acc;
}

// ---------------------------------------------------------------------------
// Fused attn+Wh GEMM (mma.sync): b[n,o] = sum_{h,m} (phiQh*invDH) * Mb
// ---------------------------------------------------------------------------
__global__ __launch_bounds__(256, 2) void fused_bh_gemm(
    const float* __restrict__ Yq,
    const float* __restrict__ invDH,
    const uint32_t* __restrict__ Bpk_h, const uint32_t* __restrict__ Bpk_l,
    float* __restrict__ bb)
{
    __shared__ uint32_t Ah[128][20], Al[128][20], Bh[128][20], Bl[128][20];

    const int tid  = threadIdx.x;
    const int lane = tid & 31;
    const int wid  = tid >> 5;
    const int wm   = wid & 3;
    const int wn   = wid >> 2;
    const int row0 = blockIdx.y * 128;
    const int col0 = blockIdx.x * 128;
    const int r    = lane >> 2;
    const int q4   = lane & 3;

    const int aRow = (lane & 15);
    const int aCol = (lane >> 4) * 4;
    const int bRow = (lane & 7) + ((lane >> 4) << 3);
    const int bCol = ((lane >> 3) & 1) * 4;

    float acc[2][8][4];
#pragma unroll
    for (int mt = 0; mt < 2; mt++)
#pragma unroll
        for (int nt = 0; nt < 8; nt++)
#pragma unroll
            for (int i = 0; i < 4; i++) acc[mt][nt][i] = 0.f;

    for (int kt = 0; kt < 60; kt++) {
        int k0 = kt * 32;
#pragma unroll
        for (int i = 0; i < 8; i++) {
            int idx = tid + i * 256;
            int m = idx >> 4, kp = idx & 15;
            int gm = row0 + m;
            int gk = k0 + kp * 2;
            int h  = gk / OSD;
            int col = gk - h * OSD;
            float x0 = 0.f, x1 = 0.f;
            if (gm < NROWS) {
                float sc = invDH[gm * HH + h];
                const float* p = Yq + (long)gm * FF + h * DD + SD + col;
                x0 = p[0] * sc;
                x1 = p[1] * sc;
            }
            uint32_t hp, lp; cvt_pack(x0, x1, hp, lp);
            Ah[m][kp] = hp; Al[m][kp] = lp;
        }
#pragma unroll
        for (int i = 0; i < 8; i++) {
            int idx = tid + i * 256;
            int n = idx >> 4, kp = idx & 15;
            int gn = col0 + n;
            int gkp = kt * 16 + kp;
            bool ok = (gn < OSD);
            Bh[n][kp] = ok ? __ldg(&Bpk_h[gn * CHP + gkp]) : 0u;
            Bl[n][kp] = ok ? __ldg(&Bpk_l[gn * CHP + gkp]) : 0u;
        }
        __syncthreads();

#pragma unroll
        for (int ks = 0; ks < 2; ks++) {
            uint32_t ah[2][4], al[2][4];
#pragma unroll
            for (int mt = 0; mt < 2; mt++) {
                int m_ = wm * 32 + mt * 16 + aRow;
                int c_ = ks * 8 + aCol;
                ldsm_x4(ah[mt][0], ah[mt][1], ah[mt][2], ah[mt][3], smem_addr(&Ah[m_][c_]));
                ldsm_x4(al[mt][0], al[mt][1], al[mt][2], al[mt][3], smem_addr(&Al[m_][c_]));
            }
#pragma unroll
            for (int ntp = 0; ntp < 4; ntp++) {
                int n_ = wn * 64 + ntp * 16 + bRow;
                int c_ = ks * 8 + bCol;
                uint32_t bh[4], bl[4];
                ldsm_x4(bh[0], bh[1], bh[2], bh[3], smem_addr(&Bh[n_][c_]));
                ldsm_x4(bl[0], bl[1], bl[2], bl[3], smem_addr(&Bl[n_][c_]));
#pragma unroll
                for (int sub = 0; sub < 2; sub++) {
                    int nt = ntp * 2 + sub;
#pragma unroll
                    for (int mt = 0; mt < 2; mt++) {
                        mma16816(acc[mt][nt], ah[mt], bh[sub * 2], bh[sub * 2 + 1]);
                        mma16816(acc[mt][nt], al[mt], bh[sub * 2], bh[sub * 2 + 1]);
                        mma16816(acc[mt][nt], ah[mt], bl[sub * 2], bl[sub * 2 + 1]);
                    }
                }
            }
        }
        __syncthreads();
    }

#pragma unroll
    for (int mt = 0; mt < 2; mt++) {
        int rm0 = row0 + wm * 32 + mt * 16 + r;
        int rm1 = rm0 + 8;
#pragma unroll
        for (int nt = 0; nt < 8; nt++) {
            int cn = col0 + wn * 64 + nt * 8 + q4 * 2;
#pragma unroll
            for (int jj = 0; jj < 2; jj++) {
                int gn = cn + jj;
                if (gn >= OSD) continue;
                if (rm0 < NROWS) bb[rm0 * OSD + gn] = acc[mt][nt][jj];
                if (rm1 < NROWS) bb[rm1 * OSD + gn] = acc[mt][nt][2 + jj];
            }
        }
    }
}

// --------- s-block ktv (reads compact Vs) ----------------------------------
#define KTVS_NCHUNK 100
__global__ __launch_bounds__(320) void ktvs_kernel(
    const float* __restrict__ Yk, const float* __restrict__ Vs,
    float* __restrict__ ktvs)
{
    __shared__ float sk[SD], sv[SD];
    int h  = blockIdx.y;
    int cn = blockIdx.x;
    int chunk = (NROWS + KTVS_NCHUNK - 1) / KTVS_NCHUNK;
    int n0 = cn * chunk;
    int n1 = n0 + chunk; if (n1 > NROWS) n1 = NROWS;
    int t = threadIdx.x;
    int m = t / SD, d = t - m * SD;
    bool act = (t < SD * SD);
    float acc = 0.f;
    for (int n = n0; n < n1; n++) {
        if (t < SD)            sk[t]      = Yk[(long)n * FF + h * DD + t];
        else if (t < 2 * SD)   sv[t - SD] = Vs[n * 136 + h * SD + (t - SD)];
        __syncthreads();
        if (act) acc += sk[m] * sv[d];
        __syncthreads();
    }
    if (act) atomicAdd(&ktvs[h * SD * SD + m * SD + d], acc);
}

// --------- s-part attention fused: cs = (phiQs @ ktvs) / denS --------------
__global__ void cs_kernel(const float* __restrict__ Yq,
                          const float* __restrict__ ktvs,
                          const float* __restrict__ dS,
                          float* __restrict__ cs)
{
    int warp = (blockIdx.x * blockDim.x + threadIdx.x) >> 5;
    int lane = threadIdx.x & 31;
    if (warp >= NROWS * HH) return;
    int n = warp / HH, h = warp - n * HH;
    const float* q = Yq + (long)n * FF + h * DD;
    const float* kt = ktvs + h * SD * SD;
    float qv = (lane < SD) ? q[lane] : 0.f;
    float acc = 0.f;
#pragma unroll
    for (int m = 0; m < SD; m++) {
        float qm = __shfl_sync(0xffffffffu, qv, m);
        if (lane < SD) acc += qm * kt[m * SD + lane];
    }
    if (lane < SD) cs[n * (HH * SD) + h * SD + lane] = acc / (dS[n * HH + h] + 1e-6f);
}

// --------- s-part pseudo-linear fixup on Y (stride FF) ---------------------
__global__ void ep1s_kernel(float* __restrict__ Y, int do_phi)
{
    int warp = (blockIdx.x * blockDim.x + threadIdx.x) >> 5;
    int lane = threadIdx.x & 31;
    if (warp >= NROWS * HH) return;
    int n = warp / HH, h = warp - n * HH;
    float* p = Y + (long)n * FF + h * DD;
    float x = (lane < SD) ? p[lane] : 0.f;
    float ss = x * x;
#pragma unroll
    for (int o = 16; o > 0; o >>= 1) ss += __shfl_xor_sync(0xffffffffu, ss, o);
    float scale = 1.f / (sqrtf(ss) + 1e-8f);
    if (lane < SD) {
        float y = x * scale;
        if (do_phi) y = (y > 0.f) ? y + 1.f : __expf(y);
        p[lane] = y;
    }
}

// --------- normalize compact Vs (17 per (n,h), no phi) ---------------------
__global__ void ep1sc_kernel(float* __restrict__ Vs)
{
    int warp = (blockIdx.x * blockDim.x + threadIdx.x) >> 5;
    int lane = threadIdx.x & 31;
    if (warp >= NROWS * HH) return;
    int n = warp / HH, h = warp - n * HH;
    float* p = Vs + n * 136 + h * SD;
    float x = (lane < SD) ? p[lane] : 0.f;
    float ss = x * x;
#pragma unroll
    for (int o = 16; o > 0; o >>= 1) ss += __shfl_xor_sync(0xffffffffu, ss, o);
    float scale = 1.f / (sqrtf(ss) + 1e-8f);
    if (lane < SD) p[lane] = x * scale;
}

__global__ void zero_kernel(float* __restrict__ p, int n)
{
    int i = blockIdx.x * blockDim.x + threadIdx.x;
    if (i < n) p[i] = 0.f;
}

// --------- column sums of phiK + G column 256 ------------------------------
__global__ void colsum2_kernel(const float* __restrict__ Y, const float* __restrict__ Xs,
                               float* __restrict__ out, float* __restrict__ G)
{
    int f = blockIdx.x * blockDim.x + threadIdx.x;
    if (f >= FF) return;
    int n0 = blockIdx.y * 750;
    int n1 = n0 + 750; if (n1 > NROWS) n1 = NROWS;
    float s = 0.f, s2 = 0.f;
    for (int n = n0; n < n1; n++) {
        float y = Y[(long)n * FF + f];
        s += y;
        s2 += y * Xs[(long)n * DD + 256];
    }
    atomicAdd(&out[f], s);
    int h = f / DD, c = f - h * DD;
    if (c >= SD)
        atomicAdd(&G[(long)h * OSD * GJ + (c - SD) * GJ + 256], s2);
}

// --------- den_s / inv den_h per (n,h) -------------------------------------
__global__ void den_kernel(const float* __restrict__ PQ,
                           const float* __restrict__ sumK,
                           float* __restrict__ dS, float* __restrict__ invDH)
{
    int n = blockIdx.x;
    int h = threadIdx.x >> 5;
    int lane = threadIdx.x & 31;
    const float* p = PQ + (long)n * FF + h * DD;
    const float* s = sumK + h * DD;
    float as = 0.f, ah = 0.f;
    for (int m = lane; m < DD; m += 32) {
        float v = p[m] * s[m];
        if (m < SD) as += v; else ah += v;
    }
#pragma unroll
    for (int o = 16; o > 0; o >>= 1) {
        as += __shfl_xor_sync(0xffffffffu, as, o);
        ah += __shfl_xor_sync(0xffffffffu, ah, o);
    }
    if (lane == 0) {
        dS[n * HH + h] = as;
        invDH[n * HH + h] = 1.f / (ah + 1e-8f);
    }
}

// --------- a = c_s @ Ws^T, att_s = a / max(||a||,1e-12) --------------------
__global__ void a_kernel(const float* __restrict__ cs,
                         const float* __restrict__ Ws,
                         float* __restrict__ atts)
{
    __shared__ float ws[SD * 136];
    for (int i = threadIdx.x; i < SD * 136; i += blockDim.x) ws[i] = Ws[i];
    __syncthreads();
    int warp = threadIdx.x >> 5, lane = threadIdx.x & 31;
    int n = blockIdx.x * 8 + warp;
    if (n >= NROWS) return;
    float acc[SD];
#pragma unroll
    for (int o = 0; o < SD; o++) acc[o] = 0.f;
    for (int f = lane; f < 136; f += 32) {
        float x = cs[n * 136 + f];
#pragma unroll
        for (int o = 0; o < SD; o++) acc[o] += x * ws[o * 136 + f];
    }
#pragma unroll
    for (int o = 0; o < SD; o++)
#pragma unroll
        for (int s = 16; s > 0; s >>= 1)
            acc[o] += __shfl_xor_sync(0xffffffffu, acc[o], s);
    if (lane == 0) {
        float ss = 0.f;
#pragma unroll
        for (int o = 0; o < SD; o++) ss += acc[o] * acc[o];
        float sc = 1.f / fmaxf(sqrtf(ss), 1e-12f);
#pragma unroll
        for (int o = 0; o < SD; o++) atts[n * SD + o] = acc[o] * sc;
    }
}

// --------- final epilogue ---------------------------------------------------
__global__ void final_kernel(const float* __restrict__ b,
                             const float* __restrict__ atts,
                             float* __restrict__ out)
{
    int warp = threadIdx.x >> 5, lane = threadIdx.x & 31;
    int n = blockIdx.x * 8 + warp;
    if (n >= NROWS) return;
    const float* br = b + n * OSD;
    float ss = 0.f;
    for (int j = lane; j < OSD; j += 32) { float v = br[j]; ss += v * v; }
#pragma unroll
    for (int s = 16; s > 0; s >>= 1) ss += __shfl_xor_sync(0xffffffffu, ss, s);
    float nr  = sqrtf(ss);
    float bn  = nr + 1e-8f;
    float bnc = fminf(bn, 1e6f);
    float bt  = sqrtf(bnc * bnc + 1.0f);
    float scale = (bn > 1e6f) ? (1e6f / fmaxf(nr, 1e-12f * bnc)) : 1.0f;
    float* o = out + n * DD;
    for (int j = lane; j < OSD; j += 32) o[SD + j] = br[j] * scale;
    if (lane < SD) o[lane] = bt * atts[n * SD + lane];
}

// ---------------------------------------------------------------------------
extern "C" void kernel_launch(void* const* d_in, const int* in_sizes, int n_in,
                              void* d_out, int out_size)
{
    const float* qin = (const float*)d_in[0];
    const float* sin = (const float*)d_in[1];
    const float* Wq  = (const float*)d_in[2];
    const float* Wk  = (const float*)d_in[3];
    const float* Wv  = (const float*)d_in[4];
    const float* Ws  = (const float*)d_in[5];
    const float* Wh  = (const float*)d_in[6];
    float* out = (float*)d_out;

    float *Yq, *Yk, *G, *P, *Vs, *ktvs, *sumK, *dS, *invDH, *cs, *atts, *bb, *Mb;
    uint32_t *Xqh, *Xql, *Xsh, *Xsl, *Wqh, *Wql, *Wkh, *Wkl, *WvSh, *WvSl, *Mbh, *Mbl;
    cudaGetSymbolAddress((void**)&Yq,   g_Yq);
    cudaGetSymbolAddress((void**)&Yk,   g_Yk);
    cudaGetSymbolAddress((void**)&G,    g_G);
    cudaGetSymbolAddress((void**)&P,    g_P);
    cudaGetSymbolAddress((void**)&Vs,   g_Vs);
    cudaGetSymbolAddress((void**)&ktvs, g_ktvs);
    cudaGetSymbolAddress((void**)&sumK, g_sumK);
    cudaGetSymbolAddress((void**)&dS,   g_denS);
    cudaGetSymbolAddress((void**)&invDH, g_invDH);
    cudaGetSymbolAddress((void**)&cs,   g_cs);
    cudaGetSymbolAddress((void**)&atts, g_atts);
    cudaGetSymbolAddress((void**)&bb,   g_b);
    cudaGetSymbolAddress((void**)&Mb,   g_Mb);
    cudaGetSymbolAddress((void**)&Xqh,  g_Xq_hi);  cudaGetSymbolAddress((void**)&Xql,  g_Xq_lo);
    cudaGetSymbolAddress((void**)&Xsh,  g_Xs_hi);  cudaGetSymbolAddress((void**)&Xsl,  g_Xs_lo);
    cudaGetSymbolAddress((void**)&Wqh,  g_Wq_hi);  cudaGetSymbolAddress((void**)&Wql,  g_Wq_lo);
    cudaGetSymbolAddress((void**)&Wkh,  g_Wk_hi);  cudaGetSymbolAddress((void**)&Wkl,  g_Wk_lo);
    cudaGetSymbolAddress((void**)&WvSh, g_WvS_hi); cudaGetSymbolAddress((void**)&WvSl, g_WvS_lo);
    cudaGetSymbolAddress((void**)&Mbh,  g_Mb_hi);  cudaGetSymbolAddress((void**)&Mbl,  g_Mb_lo);

    static int inited = 0;
    static cudaStream_t sB;
    static cudaEvent_t eFork, eXs, eZero, eProjK, eP, eCS, eDen, eA;
    if (!inited) {
        cudaFuncSetAttribute(gemm_pp_db, cudaFuncAttributeMaxDynamicSharedMemorySize, 2 * STAGE_BYTES);
        cudaStreamCreateWithFlags(&sB, cudaStreamNonBlocking);
        cudaEventCreateWithFlags(&eFork,  cudaEventDisableTiming);
        cudaEventCreateWithFlags(&eXs,    cudaEventDisableTiming);
        cudaEventCreateWithFlags(&eZero,  cudaEventDisableTiming);
        cudaEventCreateWithFlags(&eProjK, cudaEventDisableTiming);
        cudaEventCreateWithFlags(&eP,     cudaEventDisableTiming);
        cudaEventCreateWithFlags(&eCS,    cudaEventDisableTiming);
        cudaEventCreateWithFlags(&eDen,   cudaEventDisableTiming);
        cudaEventCreateWithFlags(&eA,     cudaEventDisableTiming);
        inited = 1;
    }

    const int rowTiles = (NROWS + 127) / 128;   // 235
    const int fTiles   = (FF + 127) / 128;      // 17
    const int KPX      = 129;                   // pairs for K=257

    // ---- fork stream B off stream 0 ----
    cudaEventRecord(eFork, 0);
    cudaStreamWaitEvent(sB, eFork, 0);

    // stream 0: pack Xs (needed by projK here + Vs gemm on B), pack Wk
    pack_kernel<<<(NROWS * LDP + 255) / 256, 256, 0, 0>>>(sin, Xsh, Xsl, NROWS, DD, DD, LDP);
    cudaEventRecord(eXs, 0);
    pack_kernel<<<(FF * LDP + 255) / 256, 256, 0, 0>>>(Wk, Wkh, Wkl, FF, DD, DD, LDP);

    // stream B: packs (Xq, Wq, WvS) + zeros + P (weights-only)
    pack_kernel<<<(NROWS * LDP + 255) / 256, 256, 0, sB>>>(qin, Xqh, Xql, NROWS, DD, DD, LDP);
    pack_kernel<<<(FF * LDP + 255) / 256, 256, 0, sB>>>(Wq, Wqh, Wql, FF, DD, DD, LDP);
    pack_wvs_kernel<<<(136 * LDP + 255) / 256, 256, 0, sB>>>(Wv, WvSh, WvSl);
    zero_kernel<<<(HH * OSD * GJ + 255) / 256, 256, 0, sB>>>(G, HH * OSD * GJ);
    zero_kernel<<<(HH * SD * SD + 255) / 256, 256, 0, sB>>>(ktvs, HH * SD * SD);
    zero_kernel<<<(FF + 255) / 256, 256, 0, sB>>>(sumK, FF);
    cudaEventRecord(eZero, sB);
    p_kernel<<<dim3(17, 15, HH), 256, 0, sB>>>(Wv, Wh, P);
    cudaEventRecord(eP, sB);

    // stream 0: projK
    gemm_pp_db<<<dim3(fTiles, rowTiles), 256, 2 * STAGE_BYTES, 0>>>(
        Xsh, Xsl, Wkh, Wkl, Yk, NROWS, FF, KPX, FF, 1);
    cudaEventRecord(eProjK, 0);

    // stream B: projQ + its s-part fixup
    gemm_pp_db<<<dim3(fTiles, rowTiles), 256, 2 * STAGE_BYTES, sB>>>(
        Xqh, Xql, Wqh, Wql, Yq, NROWS, FF, KPX, FF, 1);
    ep1s_kernel<<<NROWS, 256, 0, sB>>>(Yq, 1);

    // stream 0: G gemm (phiKh^T @ Xs) after zeros
    cudaStreamWaitEvent(0, eZero, 0);
    g_gemm<<<dim3(2, 2, HH * KTV_NSPLIT), 256, 0, 0>>>(Yk, sin, G);

    // stream B: Vs = Xs @ WvS^T, normalize; then s-chain after projK
    cudaStreamWaitEvent(sB, eXs, 0);
    gemm_pp_db<<<dim3(2, rowTiles), 256, 2 * STAGE_BYTES, sB>>>(
        Xsh, Xsl, WvSh, WvSl, Vs, NROWS, 136, KPX, 136, 0);
    ep1sc_kernel<<<NROWS, 256, 0, sB>>>(Vs);
    cudaStreamWaitEvent(sB, eProjK, 0);
    ep1s_kernel<<<NROWS, 256, 0, sB>>>(Yk, 1);
    colsum2_kernel<<<dim3((FF + 255) / 256, 40), 256, 0, sB>>>(Yk, sin, sumK, G);
    cudaEventRecord(eCS, sB);
    ktvs_kernel<<<dim3(KTVS_NCHUNK, HH), 320, 0, sB>>>(Yk, Vs, ktvs);
    den_kernel<<<NROWS, 256, 0, sB>>>(Yq, sumK, dS, invDH);
    cudaEventRecord(eDen, sB);
    cs_kernel<<<NROWS, 256, 0, sB>>>(Yq, ktvs, dS, cs);
    a_kernel<<<(NROWS + 7) / 8, 256, 0, sB>>>(cs, Ws, atts);
    cudaEventRecord(eA, sB);

    // stream 0: M = G @ P (needs G complete incl. col 256, and P), pack Mb
    cudaStreamWaitEvent(0, eCS, 0);
    cudaStreamWaitEvent(0, eP, 0);
    m_kernel<<<dim3(15, 15, HH), 256, 0, 0>>>(G, P, Mb);
    pack_kernel<<<(OSD * CHP + 255) / 256, 256, 0, 0>>>(Mb, Mbh, Mbl, OSD, HH * OSD, HH * OSD, CHP);

    // stream 0: fused attn+Wh GEMM
    cudaStreamWaitEvent(0, eDen, 0);
    fused_bh_gemm<<<dim3(2, rowTiles), 256, 0, 0>>>(Yq, invDH, Mbh, Mbl, bb);

    // stream 0: final epilogue (join stream B)
    cudaStreamWaitEvent(0, eA, 0);
    final_kernel<<<(NROWS + 7) / 8, 256, 0, 0>>>(bb, atts, out);
}

// round 16
// speedup vs baseline: 1.3371x; 1.0299x over previous
#include <cuda_runtime.h>
#include <cuda_bf16.h>
#include <stdint.h>
#include <math.h>

#define NROWS 30000
#define HH    8
#define SD    17
#define OSD   240
#define DD    257
#define FF    2056
#define LDP   144
#define CHP   960
#define GJ    264

__device__ float    g_Yq[NROWS * FF];
__device__ float    g_Yk[NROWS * FF];
__device__ float    g_G[HH * OSD * GJ];
__device__ float    g_P[HH * DD * OSD];
__device__ float    g_Vs[NROWS * 136];
__device__ float    g_ktvs[HH * SD * SD];
__device__ float    g_sumK[FF];
__device__ float    g_invDH[NROWS * HH];
__device__ float    g_cs[NROWS * HH * SD];
__device__ float    g_atts[NROWS * SD];
__device__ float    g_b[NROWS * OSD];
__device__ float    g_Mb[OSD * HH * OSD];
__device__ uint32_t g_Xq_hi[NROWS * LDP], g_Xq_lo[NROWS * LDP];
__device__ uint32_t g_Xs_hi[NROWS * LDP], g_Xs_lo[NROWS * LDP];
__device__ uint32_t g_Wq_hi[FF * LDP],    g_Wq_lo[FF * LDP];
__device__ uint32_t g_Wk_hi[FF * LDP],    g_Wk_lo[FF * LDP];
__device__ uint32_t g_WvS_hi[136 * LDP],  g_WvS_lo[136 * LDP];
__device__ uint32_t g_Mb_hi[OSD * CHP],   g_Mb_lo[OSD * CHP];

__device__ __forceinline__ void mma16816(float c[4], const uint32_t a[4], const uint32_t b0, const uint32_t b1)
{
    asm volatile(
        "mma.sync.aligned.m16n8k16.row.col.f32.bf16.bf16.f32 "
        "{%0,%1,%2,%3}, {%4,%5,%6,%7}, {%8,%9}, {%0,%1,%2,%3};\n"
        : "+f"(c[0]), "+f"(c[1]), "+f"(c[2]), "+f"(c[3])
        : "r"(a[0]), "r"(a[1]), "r"(a[2]), "r"(a[3]), "r"(b0), "r"(b1));
}

__device__ __forceinline__ void ldsm_x4(uint32_t& r0, uint32_t& r1, uint32_t& r2, uint32_t& r3, uint32_t addr)
{
    asm volatile("ldmatrix.sync.aligned.m8n8.x4.shared.b16 {%0,%1,%2,%3}, [%4];"
                 : "=r"(r0), "=r"(r1), "=r"(r2), "=r"(r3) : "r"(addr));
}

__device__ __forceinline__ uint32_t smem_addr(const void* p)
{
    return (uint32_t)__cvta_generic_to_shared(p);
}

__device__ __forceinline__ void cp_async16(uint32_t dst, const void* src, int src_bytes)
{
    asm volatile("cp.async.cg.shared.global [%0], [%1], 16, %2;"
                 :: "r"(dst), "l"(src), "r"(src_bytes));
}

__device__ __forceinline__ void cvt_pack(float x0, float x1, uint32_t& hp, uint32_t& lp)
{
    __nv_bfloat16 h0 = __float2bfloat16(x0);
    __nv_bfloat16 h1 = __float2bfloat16(x1);
    __nv_bfloat16 l0 = __float2bfloat16(x0 - __bfloat162float(h0));
    __nv_bfloat16 l1 = __float2bfloat16(x1 - __bfloat162float(h1));
    __nv_bfloat162 hh; hh.x = h0; hh.y = h1;
    __nv_bfloat162 ll; ll.x = l0; ll.y = l1;
    hp = *reinterpret_cast<uint32_t*>(&hh);
    lp = *reinterpret_cast<uint32_t*>(&ll);
}

__global__ void pack_kernel(const float* __restrict__ src,
                            uint32_t* __restrict__ hi, uint32_t* __restrict__ lo,
                            int rows, int K, int ld, int ldp)
{
    int idx = blockIdx.x * blockDim.x + threadIdx.x;
    if (idx >= rows * ldp) return;
    int r_ = idx / ldp, kp = idx - r_ * ldp;
    int k = kp * 2;
    float x0 = (k < K)     ? src[r_ * ld + k]     : 0.f;
    float x1 = (k + 1 < K) ? src[r_ * ld + k + 1] : 0.f;
    uint32_t hp, lp; cvt_pack(x0, x1, hp, lp);
    hi[idx] = hp; lo[idx] = lp;
}

__global__ void pack_wvs_kernel(const float* __restrict__ Wv,
                                uint32_t* __restrict__ hi, uint32_t* __restrict__ lo)
{
    int idx = blockIdx.x * blockDim.x + threadIdx.x;
    if (idx >= 136 * LDP) return;
    int r_ = idx / LDP, kp = idx - r_ * LDP;
    int k = kp * 2;
    const float* src = Wv + (long)((r_ / SD) * DD + (r_ % SD)) * DD;
    float x0 = (k < DD)     ? src[k]     : 0.f;
    float x1 = (k + 1 < DD) ? src[k + 1] : 0.f;
    uint32_t hp, lp; cvt_pack(x0, x1, hp, lp);
    hi[idx] = hp; lo[idx] = lp;
}

#define STAGE_BYTES 40960
#define ARR_BYTES   10240
__global__ __launch_bounds__(256, 2) void gemm_pp_db(
    const uint32_t* __restrict__ Apk_h, const uint32_t* __restrict__ Apk_l,
    const uint32_t* __restrict__ Bpk_h, const uint32_t* __restrict__ Bpk_l,
    float* __restrict__ C,
    int M, int N, int KP, int ldc, int phiH)
{
    extern __shared__ char smem[];
    const uint32_t smem_u32 = smem_addr(smem);

    const int tid  = threadIdx.x;
    const int lane = tid & 31;
    const int wid  = tid >> 5;
    const int wm   = wid & 3;
    const int wn   = wid >> 2;
    const int row0 = blockIdx.y * 128;
    const int col0 = blockIdx.x * 128;
    const int r    = lane >> 2;
    const int q4   = lane & 3;

    const int aRow = (lane & 15);
    const int aCol = (lane >> 4) * 4;
    const int bRow = (lane & 7) + ((lane >> 4) << 3);
    const int bCol = ((lane >> 3) & 1) * 4;

    float acc[2][8][4];
#pragma unroll
    for (int mt = 0; mt < 2; mt++)
#pragma unroll
        for (int nt = 0; nt < 8; nt++)
#pragma unroll
            for (int i = 0; i < 4; i++) acc[mt][nt][i] = 0.f;

    const int KT = (KP + 15) >> 4;

    auto fill = [&](int kt, int s) {
        int kp0 = kt * 16;
        uint32_t stage = smem_u32 + s * STAGE_BYTES;
#pragma unroll
        for (int t = 0; t < 2; t++) {
            int ci  = tid + t * 256;
            int m   = ci >> 2;
            int cp4 = (ci & 3) * 4;
            uint32_t doff = (uint32_t)(m * 20 + cp4) * 4u;
            int gm = row0 + m;
            long aoff = (long)gm * LDP + kp0 + cp4;
            int szA = (gm < M) ? 16 : 0;
            cp_async16(stage + doff,                 Apk_h + aoff, szA);
            cp_async16(stage + ARR_BYTES + doff,     Apk_l + aoff, szA);
            int gn = col0 + m;
            long boff = (long)gn * LDP + kp0 + cp4;
            int szB = (gn < N) ? 16 : 0;
            cp_async16(stage + 2 * ARR_BYTES + doff, Bpk_h + boff, szB);
            cp_async16(stage + 3 * ARR_BYTES + doff, Bpk_l + boff, szB);
        }
    };

    fill(0, 0);
    asm volatile("cp.async.commit_group;");

    for (int kt = 0; kt < KT; kt++) {
        int s = kt & 1;
        if (kt + 1 < KT) {
            fill(kt + 1, (kt + 1) & 1);
            asm volatile("cp.async.commit_group;");
            asm volatile("cp.async.wait_group 1;");
        } else {
            asm volatile("cp.async.wait_group 0;");
        }
        __syncthreads();

        uint32_t baseAh = smem_u32 + s * STAGE_BYTES;
        uint32_t baseAl = baseAh + ARR_BYTES;
        uint32_t baseBh = baseAh + 2 * ARR_BYTES;
        uint32_t baseBl = baseAh + 3 * ARR_BYTES;

#pragma unroll
        for (int ks = 0; ks < 2; ks++) {
            uint32_t ah[2][4], al[2][4];
#pragma unroll
            for (int mt = 0; mt < 2; mt++) {
                uint32_t off = (uint32_t)((wm * 32 + mt * 16 + aRow) * 20 + ks * 8 + aCol) * 4u;
                ldsm_x4(ah[mt][0], ah[mt][1], ah[mt][2], ah[mt][3], baseAh + off);
                ldsm_x4(al[mt][0], al[mt][1], al[mt][2], al[mt][3], baseAl + off);
            }
#pragma unroll
            for (int ntp = 0; ntp < 4; ntp++) {
                uint32_t off = (uint32_t)((wn * 64 + ntp * 16 + bRow) * 20 + ks * 8 + bCol) * 4u;
                uint32_t bh[4], bl[4];
                ldsm_x4(bh[0], bh[1], bh[2], bh[3], baseBh + off);
                ldsm_x4(bl[0], bl[1], bl[2], bl[3], baseBl + off);
#pragma unroll
                for (int sub = 0; sub < 2; sub++) {
                    int nt = ntp * 2 + sub;
#pragma unroll
                    for (int mt = 0; mt < 2; mt++) {
                        mma16816(acc[mt][nt], ah[mt], bh[sub * 2], bh[sub * 2 + 1]);
                        mma16816(acc[mt][nt], al[mt], bh[sub * 2], bh[sub * 2 + 1]);
                        mma16816(acc[mt][nt], ah[mt], bl[sub * 2], bl[sub * 2 + 1]);
                    }
                }
            }
        }
        __syncthreads();
    }

#pragma unroll
    for (int mt = 0; mt < 2; mt++) {
        int rm0 = row0 + wm * 32 + mt * 16 + r;
        int rm1 = rm0 + 8;
#pragma unroll
        for (int nt = 0; nt < 8; nt++) {
            int cn = col0 + wn * 64 + nt * 8 + q4 * 2;
#pragma unroll
            for (int jj = 0; jj < 2; jj++) {
                int gn = cn + jj;
                if (gn >= N) continue;
                bool phi = phiH && (gn % DD) >= SD;
                if (rm0 < M) {
                    float v = acc[mt][nt][jj];
                    if (phi) v = (v > 0.f) ? v + 1.f : __expf(v);
                    C[(long)rm0 * ldc + gn] = v;
                }
                if (rm1 < M) {
                    float v = acc[mt][nt][2 + jj];
                    if (phi) v = (v > 0.f) ? v + 1.f : __expf(v);
                    C[(long)rm1 * ldc + gn] = v;
                }
            }
        }
    }
}

#define KTV_NSPLIT 20
__global__ __launch_bounds__(256, 2) void g_gemm(
    const float* __restrict__ Yk, const float* __restrict__ Xs,
    float* __restrict__ G)
{
    __shared__ uint32_t Ah[128][20], Al[128][20], Bh[128][20], Bl[128][20];

    const int h  = blockIdx.z / KTV_NSPLIT;
    const int sp = blockIdx.z % KTV_NSPLIT;
    const int m0 = blockIdx.x * 128;
    const int j0 = blockIdx.y * 128;
    const int chunk = (NROWS + KTV_NSPLIT - 1) / KTV_NSPLIT;
    const int n0 = sp * chunk;
    int n1 = n0 + chunk; if (n1 > NROWS) n1 = NROWS;

    const float* Kp = Yk + h * DD + SD;

    const int tid  = threadIdx.x;
    const int lane = tid & 31;
    const int wid  = tid >> 5;
    const int wm   = wid & 3;
    const int wn   = wid >> 2;
    const int r    = lane >> 2;
    const int q4   = lane & 3;

    const int aRow = (lane & 15);
    const int aCol = (lane >> 4) * 4;
    const int bRow = (lane & 7) + ((lane >> 4) << 3);
    const int bCol = ((lane >> 3) & 1) * 4;

    float acc[2][8][4];
#pragma unroll
    for (int mt = 0; mt < 2; mt++)
#pragma unroll
        for (int nt = 0; nt < 8; nt++)
#pragma unroll
            for (int i = 0; i < 4; i++) acc[mt][nt][i] = 0.f;

    for (int kb = n0; kb < n1; kb += 32) {
#pragma unroll
        for (int i = 0; i < 8; i++) {
            int idx = tid + i * 256;
            int m = idx & 127, np = idx >> 7;
            int gm = m0 + m;
            int gn = kb + np * 2;
            bool mok = (gm < OSD);
            float x0 = (mok && gn     < n1) ? __ldg(&Kp[(long)gn * FF + gm])       : 0.f;
            float x1 = (mok && gn + 1 < n1) ? __ldg(&Kp[(long)(gn + 1) * FF + gm]) : 0.f;
            uint32_t hp, lp; cvt_pack(x0, x1, hp, lp);
            Ah[m][np] = hp; Al[m][np] = lp;
        }
#pragma unroll
        for (int i = 0; i < 8; i++) {
            int idx = tid + i * 256;
            int d = idx & 127, np = idx >> 7;
            int gj = j0 + d;
            int gn = kb + np * 2;
            bool jok = (gj < 256);
            float x0 = (jok && gn     < n1) ? __ldg(&Xs[(long)gn * DD + gj])       : 0.f;
            float x1 = (jok && gn + 1 < n1) ? __ldg(&Xs[(long)(gn + 1) * DD + gj]) : 0.f;
            uint32_t hp, lp; cvt_pack(x0, x1, hp, lp);
            Bh[d][np] = hp; Bl[d][np] = lp;
        }
        __syncthreads();

#pragma unroll
        for (int ks = 0; ks < 2; ks++) {
            uint32_t ah[2][4], al[2][4];
#pragma unroll
            for (int mt = 0; mt < 2; mt++) {
                int m_ = wm * 32 + mt * 16 + aRow;
                int c_ = ks * 8 + aCol;
                ldsm_x4(ah[mt][0], ah[mt][1], ah[mt][2], ah[mt][3], smem_addr(&Ah[m_][c_]));
                ldsm_x4(al[mt][0], al[mt][1], al[mt][2], al[mt][3], smem_addr(&Al[m_][c_]));
            }
#pragma unroll
            for (int ntp = 0; ntp < 4; ntp++) {
                int n_ = wn * 64 + ntp * 16 + bRow;
                int c_ = ks * 8 + bCol;
                uint32_t bh[4], bl[4];
                ldsm_x4(bh[0], bh[1], bh[2], bh[3], smem_addr(&Bh[n_][c_]));
                ldsm_x4(bl[0], bl[1], bl[2], bl[3], smem_addr(&Bl[n_][c_]));
#pragma unroll
                for (int sub = 0; sub < 2; sub++) {
                    int nt = ntp * 2 + sub;
#pragma unroll
                    for (int mt = 0; mt < 2; mt++) {
                        mma16816(acc[mt][nt], ah[mt], bh[sub * 2], bh[sub * 2 + 1]);
                        mma16816(acc[mt][nt], al[mt], bh[sub * 2], bh[sub * 2 + 1]);
                        mma16816(acc[mt][nt], ah[mt], bl[sub * 2], bl[sub * 2 + 1]);
                    }
                }
            }
        }
        __syncthreads();
    }

    float* Gp = G + (long)h * OSD * GJ;
#pragma unroll
    for (int mt = 0; mt < 2; mt++) {
        int gm0 = m0 + wm * 32 + mt * 16 + r;
        int gm1 = gm0 + 8;
#pragma unroll
        for (int nt = 0; nt < 8; nt++) {
            int gj = j0 + wn * 64 + nt * 8 + q4 * 2;
#pragma unroll
            for (int jj = 0; jj < 2; jj++) {
                int j = gj + jj;
                if (j >= 256) continue;
                if (gm0 < OSD) atomicAdd(&Gp[gm0 * GJ + j], acc[mt][nt][jj]);
                if (gm1 < OSD) atomicAdd(&Gp[gm1 * GJ + j], acc[mt][nt][2 + jj]);
            }
        }
    }
}

__global__ __launch_bounds__(256) void p_kernel(
    const float* __restrict__ Wv, const float* __restrict__ Wh,
    float* __restrict__ P)
{
    __shared__ float At[16][17], Bt[16][17];
    int h  = blockIdx.z;
    int j0 = blockIdx.x * 16;
    int o0 = blockIdx.y * 16;
    int tx = threadIdx.x & 15, ty = threadIdx.x >> 4;
    float acc = 0.f;
    for (int d0 = 0; d0 < OSD; d0 += 16) {
        int j = j0 + tx;
        At[ty][tx] = (j < DD) ? Wv[((long)h * DD + SD + d0 + ty) * DD + j] : 0.f;
        Bt[ty][tx] = Wh[(long)(o0 + tx) * (HH * OSD) + h * OSD + d0 + ty];
        __syncthreads();
#pragma unroll
        for (int dd = 0; dd < 16; dd++) acc += At[dd][tx] * Bt[dd][ty];
        __syncthreads();
    }
    int j = j0 + tx;
    if (j < DD) P[(long)h * DD * OSD + (long)j * OSD + (o0 + ty)] = acc;
}

__global__ __launch_bounds__(256) void m_kernel(
    const float* __restrict__ G, const float* __restrict__ P,
    float* __restrict__ Mb)
{
    __shared__ float At[16][17], Bt[16][17];
    int h  = blockIdx.z;
    int m0 = blockIdx.x * 16;
    int o0 = blockIdx.y * 16;
    int tx = threadIdx.x & 15, ty = threadIdx.x >> 4;
    const float* Gp = G + (long)h * OSD * GJ;
    const float* Pp = P + (long)h * DD * OSD;
    float acc = 0.f;
    for (int j0 = 0; j0 < GJ; j0 += 16) {
        int j = j0 + ty;
        At[ty][tx] = (j < GJ) ? Gp[(m0 + tx) * GJ + j] : 0.f;
        Bt[ty][tx] = (j < DD) ? Pp[(long)j * OSD + (o0 + tx)] : 0.f;
        __syncthreads();
#pragma unroll
        for (int dd = 0; dd < 16; dd++) acc += At[dd][tx] * Bt[dd][ty];
        __syncthreads();
    }
    Mb[(long)(o0 + ty) * (HH * OSD) + h * OSD + (m0 + tx)] = acc;
}

__global__ __launch_bounds__(256, 2) void fused_bh_gemm(
    const float* __restrict__ Yq,
    const float* __restrict__ invDH,
    const uint32_t* __restrict__ Bpk_h, const uint32_t* __restrict__ Bpk_l,
    float* __restrict__ bb)
{
    __shared__ uint32_t Ah[128][20], Al[128][20], Bh[128][20], Bl[128][20];

    const int tid  = threadIdx.x;
    const int lane = tid & 31;
    const int wid  = tid >> 5;
    const int wm   = wid & 3;
    const int wn   = wid >> 2;
    const int row0 = blockIdx.y * 128;
    const int col0 = blockIdx.x * 128;
    const int r    = lane >> 2;
    const int q4   = lane & 3;

    const int aRow = (lane & 15);
    const int aCol = (lane >> 4) * 4;
    const int bRow = (lane & 7) + ((lane >> 4) << 3);
    const int bCol = ((lane >> 3) & 1) * 4;

    float acc[2][8][4];
#pragma unroll
    for (int mt = 0; mt < 2; mt++)
#pragma unroll
        for (int nt = 0; nt < 8; nt++)
#pragma unroll
            for (int i = 0; i < 4; i++) acc[mt][nt][i] = 0.f;

    for (int kt = 0; kt < 60; kt++) {
        int k0 = kt * 32;
#pragma unroll
        for (int i = 0; i < 8; i++) {
            int idx = tid + i * 256;
            int m = idx >> 4, kp = idx & 15;
            int gm = row0 + m;
            int gk = k0 + kp * 2;
            int h  = gk / OSD;
            int col = gk - h * OSD;
            float x0 = 0.f, x1 = 0.f;
            if (gm < NROWS) {
                float sc = invDH[gm * HH + h];
                const float* p = Yq + (long)gm * FF + h * DD + SD + col;
                x0 = p[0] * sc;
                x1 = p[1] * sc;
            }
            uint32_t hp, lp; cvt_pack(x0, x1, hp, lp);
            Ah[m][kp] = hp; Al[m][kp] = lp;
        }
#pragma unroll
        for (int i = 0; i < 8; i++) {
            int idx = tid + i * 256;
            int n = idx >> 4, kp = idx & 15;
            int gn = col0 + n;
            int gkp = kt * 16 + kp;
            bool ok = (gn < OSD);
            Bh[n][kp] = ok ? __ldg(&Bpk_h[gn * CHP + gkp]) : 0u;
            Bl[n][kp] = ok ? __ldg(&Bpk_l[gn * CHP + gkp]) : 0u;
        }
        __syncthreads();

#pragma unroll
        for (int ks = 0; ks < 2; ks++) {
            uint32_t ah[2][4], al[2][4];
#pragma unroll
            for (int mt = 0; mt < 2; mt++) {
                int m_ = wm * 32 + mt * 16 + aRow;
                int c_ = ks * 8 + aCol;
                ldsm_x4(ah[mt][0], ah[mt][1], ah[mt][2], ah[mt][3], smem_addr(&Ah[m_][c_]));
                ldsm_x4(al[mt][0], al[mt][1], al[mt][2], al[mt][3], smem_addr(&Al[m_][c_]));
            }
#pragma unroll
            for (int ntp = 0; ntp < 4; ntp++) {
                int n_ = wn * 64 + ntp * 16 + bRow;
                int c_ = ks * 8 + bCol;
                uint32_t bh[4], bl[4];
                ldsm_x4(bh[0], bh[1], bh[2], bh[3], smem_addr(&Bh[n_][c_]));
                ldsm_x4(bl[0], bl[1], bl[2], bl[3], smem_addr(&Bl[n_][c_]));
#pragma unroll
                for (int sub = 0; sub < 2; sub++) {
                    int nt = ntp * 2 + sub;
#pragma unroll
                    for (int mt = 0; mt < 2; mt++) {
                        mma16816(acc[mt][nt], ah[mt], bh[sub * 2], bh[sub * 2 + 1]);
                        mma16816(acc[mt][nt], al[mt], bh[sub * 2], bh[sub * 2 + 1]);
                        mma16816(acc[mt][nt], ah[mt], bl[sub * 2], bl[sub * 2 + 1]);
                    }
                }
            }
        }
        __syncthreads();
    }

#pragma unroll
    for (int mt = 0; mt < 2; mt++) {
        int rm0 = row0 + wm * 32 + mt * 16 + r;
        int rm1 = rm0 + 8;
#pragma unroll
        for (int nt = 0; nt < 8; nt++) {
            int cn = col0 + wn * 64 + nt * 8 + q4 * 2;
#pragma unroll
            for (int jj = 0; jj < 2; jj++) {
                int gn = cn + jj;
                if (gn >= OSD) continue;
                if (rm0 < NROWS) bb[rm0 * OSD + gn] = acc[mt][nt][jj];
                if (rm1 < NROWS) bb[rm1 * OSD + gn] = acc[mt][nt][2 + jj];
            }
        }
    }
}

#define KTVS_NCHUNK 100
__global__ __launch_bounds__(320) void ktvs_kernel(
    const float* __restrict__ Yk, const float* __restrict__ Vs,
    float* __restrict__ ktvs)
{
    __shared__ float sk[SD], sv[SD];
    int h  = blockIdx.y;
    int cn = blockIdx.x;
    int chunk = (NROWS + KTVS_NCHUNK - 1) / KTVS_NCHUNK;
    int n0 = cn * chunk;
    int n1 = n0 + chunk; if (n1 > NROWS) n1 = NROWS;
    int t = threadIdx.x;
    int m = t / SD, d = t - m * SD;
    bool act = (t < SD * SD);
    float acc = 0.f;
    for (int n = n0; n < n1; n++) {
        if (t < SD)            sk[t]      = Yk[(long)n * FF + h * DD + t];
        else if (t < 2 * SD)   sv[t - SD] = Vs[n * 136 + h * SD + (t - SD)];
        __syncthreads();
        if (act) acc += sk[m] * sv[d];
        __syncthreads();
    }
    if (act) atomicAdd(&ktvs[h * SD * SD + m * SD + d], acc);
}

// MERGED den+cs (s-part normalized+phi'd in registers; no write-back)
__global__ void den_cs_kernel(const float* __restrict__ Yq,
                              const float* __restrict__ sumK,
                              const float* __restrict__ ktvs,
                              float* __restrict__ invDH,
                              float* __restrict__ cs)
{
    int n = blockIdx.x;
    int h = threadIdx.x >> 5;
    int lane = threadIdx.x & 31;
    const float* q  = Yq + (long)n * FF + h * DD;
    const float* sk = sumK + h * DD;

    float x = (lane < SD) ? q[lane] : 0.f;
    float ss = x * x;
#pragma unroll
    for (int o = 16; o > 0; o >>= 1) ss += __shfl_xor_sync(0xffffffffu, ss, o);
    float scale = 1.f / (sqrtf(ss) + 1e-8f);
    float sphi = 0.f;
    if (lane < SD) {
        float y = x * scale;
        sphi = (y > 0.f) ? y + 1.f : __expf(y);
    }

    float as = (lane < SD) ? sphi * sk[lane] : 0.f;
    float ah = 0.f;
    for (int m = SD + lane; m < DD; m += 32) ah += q[m] * sk[m];
#pragma unroll
    for (int o = 16; o > 0; o >>= 1) {
        as += __shfl_xor_sync(0xffffffffu, as, o);
        ah += __shfl_xor_sync(0xffffffffu, ah, o);
    }
    if (lane == 0) invDH[n * HH + h] = 1.f / (ah + 1e-8f);

    const float* kt = ktvs + h * SD * SD;
    float acc = 0.f;
#pragma unroll
    for (int m = 0; m < SD; m++) {
        float qm = __shfl_sync(0xffffffffu, sphi, m);
        if (lane < SD) acc += qm * kt[m * SD + lane];
    }
    if (lane < SD) cs[n * (HH * SD) + h * SD + lane] = acc / (as + 1e-6f);
}

__global__ void ep1s_kernel(float* __restrict__ Y, int do_phi)
{
    int warp = (blockIdx.x * blockDim.x + threadIdx.x) >> 5;
    int lane = threadIdx.x & 31;
    if (warp >= NROWS * HH) return;
    int n = warp / HH, h = warp - n * HH;
    float* p = Y + (long)n * FF + h * DD;
    float x = (lane < SD) ? p[lane] : 0.f;
    float ss = x * x;
#pragma unroll
    for (int o = 16; o > 0; o >>= 1) ss += __shfl_xor_sync(0xffffffffu, ss, o);
    float scale = 1.f / (sqrtf(ss) + 1e-8f);
    if (lane < SD) {
        float y = x * scale;
        if (do_phi) y = (y > 0.f) ? y + 1.f : __expf(y);
        p[lane] = y;
    }
}

__global__ void ep1sc_kernel(float* __restrict__ Vs)
{
    int warp = (blockIdx.x * blockDim.x + threadIdx.x) >> 5;
    int lane = threadIdx.x & 31;
    if (warp >= NROWS * HH) return;
    int n = warp / HH, h = warp - n * HH;
    float* p = Vs + n * 136 + h * SD;
    float x = (lane < SD) ? p[lane] : 0.f;
    float ss = x * x;
#pragma unroll
    for (int o = 16; o > 0; o >>= 1) ss += __shfl_xor_sync(0xffffffffu, ss, o);
    float scale = 1.f / (sqrtf(ss) + 1e-8f);
    if (lane < SD) p[lane] = x * scale;
}

__global__ void zero_kernel(float* __restrict__ p, int n)
{
    int i = blockIdx.x * blockDim.x + threadIdx.x;
    if (i < n) p[i] = 0.f;
}

__global__ void colsum2_kernel(const float* __restrict__ Y, const float* __restrict__ Xs,
                               float* __restrict__ out, float* __restrict__ G)
{
    __shared__ float xcol[750];
    int n0 = blockIdx.y * 750;
    int n1 = n0 + 750; if (n1 > NROWS) n1 = NROWS;
    for (int i = threadIdx.x; i < n1 - n0; i += blockDim.x)
        xcol[i] = Xs[(long)(n0 + i) * DD + 256];
    __syncthreads();

    int f = blockIdx.x * blockDim.x + threadIdx.x;
    if (f >= FF) return;
    float s = 0.f, s2 = 0.f;
    for (int n = n0; n < n1; n++) {
        float y = Y[(long)n * FF + f];
        s += y;
        s2 += y * xcol[n - n0];
    }
    atomicAdd(&out[f], s);
    int h = f / DD, c = f - h * DD;
    if (c >= SD)
        atomicAdd(&G[(long)h * OSD * GJ + (c - SD) * GJ + 256], s2);
}

__global__ void a_kernel(const float* __restrict__ cs,
                         const float* __restrict__ Ws,
                         float* __restrict__ atts)
{
    __shared__ float ws[SD * 136];
    for (int i = threadIdx.x; i < SD * 136; i += blockDim.x) ws[i] = Ws[i];
    __syncthreads();
    int warp = threadIdx.x >> 5, lane = threadIdx.x & 31;
    int n = blockIdx.x * 8 + warp;
    if (n >= NROWS) return;
    float acc[SD];
#pragma unroll
    for (int o = 0; o < SD; o++) acc[o] = 0.f;
    for (int f = lane; f < 136; f += 32) {
        float x = cs[n * 136 + f];
#pragma unroll
        for (int o = 0; o < SD; o++) acc[o] += x * ws[o * 136 + f];
    }
#pragma unroll
    for (int o = 0; o < SD; o++)
#pragma unroll
        for (int s = 16; s > 0; s >>= 1)
            acc[o] += __shfl_xor_sync(0xffffffffu, acc[o], s);
    if (lane == 0) {
        float ss = 0.f;
#pragma unroll
        for (int o = 0; o < SD; o++) ss += acc[o] * acc[o];
        float sc = 1.f / fmaxf(sqrtf(ss), 1e-12f);
#pragma unroll
        for (int o = 0; o < SD; o++) atts[n * SD + o] = acc[o] * sc;
    }
}

__global__ void final_kernel(const float* __restrict__ b,
                             const float* __restrict__ atts,
                             float* __restrict__ out)
{
    int warp = threadIdx.x >> 5, lane = threadIdx.x & 31;
    int n = blockIdx.x * 8 + warp;
    if (n >= NROWS) return;
    const float* br = b + n * OSD;
    float ss = 0.f;
    for (int j = lane; j < OSD; j += 32) { float v = br[j]; ss += v * v; }
#pragma unroll
    for (int s = 16; s > 0; s >>= 1) ss += __shfl_xor_sync(0xffffffffu, ss, s);
    float nr  = sqrtf(ss);
    float bn  = nr + 1e-8f;
    float bnc = fminf(bn, 1e6f);
    float bt  = sqrtf(bnc * bnc + 1.0f);
    float scale = (bn > 1e6f) ? (1e6f / fmaxf(nr, 1e-12f * bnc)) : 1.0f;
    float* o = out + n * DD;
    for (int j = lane; j < OSD; j += 32) o[SD + j] = br[j] * scale;
    if (lane < SD) o[lane] = bt * atts[n * SD + lane];
}

extern "C" void kernel_launch(void* const* d_in, const int* in_sizes, int n_in,
                              void* d_out, int out_size)
{
    const float* qin = (const float*)d_in[0];
    const float* sin = (const float*)d_in[1];
    const float* Wq  = (const float*)d_in[2];
    const float* Wk  = (const float*)d_in[3];
    const float* Wv  = (const float*)d_in[4];
    const float* Ws  = (const float*)d_in[5];
    const float* Wh  = (const float*)d_in[6];
    float* out = (float*)d_out;

    float *Yq, *Yk, *G, *P, *Vs, *ktvs, *sumK, *invDH, *cs, *atts, *bb, *Mb;
    uint32_t *Xqh, *Xql, *Xsh, *Xsl, *Wqh, *Wql, *Wkh, *Wkl, *WvSh, *WvSl, *Mbh, *Mbl;
    cudaGetSymbolAddress((void**)&Yq,   g_Yq);
    cudaGetSymbolAddress((void**)&Yk,   g_Yk);
    cudaGetSymbolAddress((void**)&G,    g_G);
    cudaGetSymbolAddress((void**)&P,    g_P);
    cudaGetSymbolAddress((void**)&Vs,   g_Vs);
    cudaGetSymbolAddress((void**)&ktvs, g_ktvs);
    cudaGetSymbolAddress((void**)&sumK, g_sumK);
    cudaGetSymbolAddress((void**)&invDH, g_invDH);
    cudaGetSymbolAddress((void**)&cs,   g_cs);
    cudaGetSymbolAddress((void**)&atts, g_atts);
    cudaGetSymbolAddress((void**)&bb,   g_b);
    cudaGetSymbolAddress((void**)&Mb,   g_Mb);
    cudaGetSymbolAddress((void**)&Xqh,  g_Xq_hi);  cudaGetSymbolAddress((void**)&Xql,  g_Xq_lo);
    cudaGetSymbolAddress((void**)&Xsh,  g_Xs_hi);  cudaGetSymbolAddress((void**)&Xsl,  g_Xs_lo);
    cudaGetSymbolAddress((void**)&Wqh,  g_Wq_hi);  cudaGetSymbolAddress((void**)&Wql,  g_Wq_lo);
    cudaGetSymbolAddress((void**)&Wkh,  g_Wk_hi);  cudaGetSymbolAddress((void**)&Wkl,  g_Wk_lo);
    cudaGetSymbolAddress((void**)&WvSh, g_WvS_hi); cudaGetSymbolAddress((void**)&WvSl, g_WvS_lo);
    cudaGetSymbolAddress((void**)&Mbh,  g_Mb_hi);  cudaGetSymbolAddress((void**)&Mbl,  g_Mb_lo);

    static int inited = 0;
    static cudaStream_t sB;
    static cudaEvent_t eFork, eXs, eZero, eProjK, eP, eCS, eDen, eA;
    if (!inited) {
        cudaFuncSetAttribute(gemm_pp_db, cudaFuncAttributeMaxDynamicSharedMemorySize, 2 * STAGE_BYTES);
        cudaStreamCreateWithFlags(&sB, cudaStreamNonBlocking);
        cudaEventCreateWithFlags(&eFork,  cudaEventDisableTiming);
        cudaEventCreateWithFlags(&eXs,    cudaEventDisableTiming);
        cudaEventCreateWithFlags(&eZero,  cudaEventDisableTiming);
        cudaEventCreateWithFlags(&eProjK, cudaEventDisableTiming);
        cudaEventCreateWithFlags(&eP,     cudaEventDisableTiming);
        cudaEventCreateWithFlags(&eCS,    cudaEventDisableTiming);
        cudaEventCreateWithFlags(&eDen,   cudaEventDisableTiming);
        cudaEventCreateWithFlags(&eA,     cudaEventDisableTiming);
        inited = 1;
    }

    const int rowTiles = (NROWS + 127) / 128;   // 235
    const int fTiles   = (FF + 127) / 128;      // 17
    const int KPX      = 129;

    cudaEventRecord(eFork, 0);
    cudaStreamWaitEvent(sB, eFork, 0);

    // Launches 1-5: packs (ncu "-s 5 -c 1" lands on projK at launch 6)
    pack_kernel<<<(NROWS * LDP + 255) / 256, 256, 0, 0>>>(sin, Xsh, Xsl, NROWS, DD, DD, LDP);
    cudaEventRecord(eXs, 0);
    pack_kernel<<<(FF * LDP + 255) / 256, 256, 0, 0>>>(Wk, Wkh, Wkl, FF, DD, DD, LDP);
    pack_kernel<<<(NROWS * LDP + 255) / 256, 256, 0, sB>>>(qin, Xqh, Xql, NROWS, DD, DD, LDP);
    pack_kernel<<<(FF * LDP + 255) / 256, 256, 0, sB>>>(Wq, Wqh, Wql, FF, DD, DD, LDP);
    pack_wvs_kernel<<<(136 * LDP + 255) / 256, 256, 0, sB>>>(Wv, WvSh, WvSl);

    // Launch 6 (stream 0): projK — ncu target
    gemm_pp_db<<<dim3(fTiles, rowTiles), 256, 2 * STAGE_BYTES, 0>>>(
        Xsh, Xsl, Wkh, Wkl, Yk, NROWS, FF, KPX, FF, 1);
    cudaEventRecord(eProjK, 0);

    // stream B: zeros + P + projQ
    zero_kernel<<<(HH * OSD * GJ + 255) / 256, 256, 0, sB>>>(G, HH * OSD * GJ);
    zero_kernel<<<(HH * SD * SD + 255) / 256, 256, 0, sB>>>(ktvs, HH * SD * SD);
    zero_kernel<<<(FF + 255) / 256, 256, 0, sB>>>(sumK, FF);
    cudaEventRecord(eZero, sB);
    p_kernel<<<dim3(17, 15, HH), 256, 0, sB>>>(Wv, Wh, P);
    cudaEventRecord(eP, sB);
    gemm_pp_db<<<dim3(fTiles, rowTiles), 256, 2 * STAGE_BYTES, sB>>>(
        Xqh, Xql, Wqh, Wql, Yq, NROWS, FF, KPX, FF, 1);

    // stream 0: G gemm after zeros
    cudaStreamWaitEvent(0, eZero, 0);
    g_gemm<<<dim3(2, 2, HH * KTV_NSPLIT), 256, 0, 0>>>(Yk, sin, G);

    // stream B: Vs gemm + normalize; s-chain after projK
    cudaStreamWaitEvent(sB, eXs, 0);
    gemm_pp_db<<<dim3(2, rowTiles), 256, 2 * STAGE_BYTES, sB>>>(
        Xsh, Xsl, WvSh, WvSl, Vs, NROWS, 136, KPX, 136, 0);
    ep1sc_kernel<<<NROWS, 256, 0, sB>>>(Vs);
    cudaStreamWaitEvent(sB, eProjK, 0);
    ep1s_kernel<<<NROWS, 256, 0, sB>>>(Yk, 1);
    colsum2_kernel<<<dim3((FF + 255) / 256, 40), 256, 0, sB>>>(Yk, sin, sumK, G);
    cudaEventRecord(eCS, sB);
    ktvs_kernel<<<dim3(KTVS_NCHUNK, HH), 320, 0, sB>>>(Yk, Vs, ktvs);
    den_cs_kernel<<<NROWS, 256, 0, sB>>>(Yq, sumK, ktvs, invDH, cs);
    cudaEventRecord(eDen, sB);
    a_kernel<<<(NROWS + 7) / 8, 256, 0, sB>>>(cs, Ws, atts);
    cudaEventRecord(eA, sB);

    // stream 0: M = G @ P, pack Mb
    cudaStreamWaitEvent(0, eCS, 0);
    cudaStreamWaitEvent(0, eP, 0);
    m_kernel<<<dim3(15, 15, HH), 256, 0, 0>>>(G, P, Mb);
    pack_kernel<<<(OSD * CHP + 255) / 256, 256, 0, 0>>>(Mb, Mbh, Mbl, OSD, HH * OSD, HH * OSD, CHP);

    // stream 0: fused attn+Wh GEMM
    cudaStreamWaitEvent(0, eDen, 0);
    fused_bh_gemm<<<dim3(2, rowTiles), 256, 0, 0>>>(Yq, invDH, Mbh, Mbl, bb);

    // stream 0: final epilogue (join stream B)
    cudaStreamWaitEvent(0, eA, 0);
    final_kernel<<<(NROWS + 7) / 8, 256, 0, 0>>>(bb, atts, out);
}